// round 10
// baseline (speedup 1.0000x reference)
#include <cuda_runtime.h>
#include <cstdint>
#include <cstddef>

// ---------------- scratch (static device memory; no allocs allowed) ----------
static __device__ float g_bufA[(size_t)128 * 524288];   // 256 MB
static __device__ float g_bufB[(size_t)128 * 524288];   // 256 MB
static __device__ float g_featT[(size_t)8 * 8192 * 64]; // 16 MB transposed features
static __device__ float g_meanb[24];
static __device__ int   g_idxb[8 * 1024 * 64];
static __device__ float g_sum[256];
static __device__ float g_sq[256];
static __device__ float g_affa[256];
static __device__ float g_affd[256];
static __device__ float g_wt[65536];                    // pre-transposed tf32 weights
static __device__ unsigned g_emax[256 * 8192];          // encoded max
static __device__ unsigned g_emin[256 * 8192];          // encoded max of -y

// ---------------- helpers ----------------------------------------------------
__device__ __forceinline__ float to_tf32(float x)
{
    uint32_t r;
    asm volatile("cvt.rna.tf32.f32 %0, %1;\n" : "=r"(r) : "f"(x));
    return __uint_as_float(r);
}
__device__ __forceinline__ void mma_tf32(float* d, const uint32_t* a, const uint32_t* b)
{
    asm volatile(
        "mma.sync.aligned.m16n8k8.row.col.f32.tf32.tf32.f32 "
        "{%0,%1,%2,%3}, {%4,%5,%6,%7}, {%8,%9}, {%0,%1,%2,%3};\n"
        : "+f"(d[0]), "+f"(d[1]), "+f"(d[2]), "+f"(d[3])
        : "r"(a[0]), "r"(a[1]), "r"(a[2]), "r"(a[3]),
          "r"(b[0]), "r"(b[1]));
}
__device__ __forceinline__ void cp16(void* dst, const void* src)
{
    uint32_t d = (uint32_t)__cvta_generic_to_shared(dst);
    asm volatile("cp.async.ca.shared.global [%0], [%1], 16;\n" :: "r"(d), "l"(src));
}
__device__ __forceinline__ unsigned encf(float f)
{
    unsigned u = __float_as_uint(f);
    return (u >> 31) ? ~u : (u | 0x80000000u);
}
__device__ __forceinline__ float decf(unsigned u)
{
    return __uint_as_float((u >> 31) ? (u & 0x7FFFFFFFu) : ~u);
}

// ---------------- prep: all weight transposes + feat transpose + stat zero ---
// blocks [0,256): weight prep for 6 layers; blocks [256,4352): feat transpose
__global__ void prep_kernel(const float* __restrict__ w0, const float* __restrict__ w1,
                            const float* __restrict__ w2, const float* __restrict__ w3,
                            const float* __restrict__ w4, const float* __restrict__ w5,
                            const float* __restrict__ feat,
                            float* __restrict__ wt, float* __restrict__ featT,
                            float* __restrict__ sum, float* __restrict__ sq)
{
    int blk = blockIdx.x, tid = threadIdx.x;
    if (blk == 0) { sum[tid] = 0.f; sq[tid] = 0.f; }
    if (blk < 256) {
        const int lo[6]   = {0, 24, 40, 72, 96, 128};
        const int Os[6]   = {64, 64, 128, 64, 128, 256};
        const int Is[6]   = {67, 64, 64, 67, 64, 128};
        const int Ip[6]   = {96, 64, 64, 96, 64, 128};
        const int woff[6] = {0, 6144, 10240, 18432, 24576, 32768};
        const float* Ws[6] = {w0, w1, w2, w3, w4, w5};
        int li = 5;
#pragma unroll
        for (int i = 1; i < 6; ++i) if (blk < lo[i]) { li = i - 1; break; }
        int e = (blk - lo[li]) * 256 + tid;
        int O = Os[li], I = Is[li], Ipad = Ip[li];
        if (e < Ipad * O) {
            int k = e / O, o = e % O;
            wt[woff[li] + e] = (k < I) ? to_tf32(Ws[li][(size_t)o * I + k]) : 0.f;
        }
    } else {
        __shared__ float tile[32][33];
        int t = blk - 256;                 // [0,4096)
        int b = t >> 9;
        int rem = t & 511;
        int c0 = (rem >> 8) * 32;
        int p0 = (rem & 255) * 32;
        int tx = tid & 31, ty = tid >> 5;  // 32 x 8
#pragma unroll
        for (int i = ty; i < 32; i += 8)
            tile[i][tx] = feat[((size_t)b * 64 + c0 + i) * 8192 + p0 + tx];
        __syncthreads();
#pragma unroll
        for (int i = ty; i < 32; i += 8)
            featT[((size_t)b * 8192 + p0 + i) * 64 + c0 + tx] = tile[tx][i];
    }
}

// ---------------- mean over N of xyz ----------------------------------------
__global__ void mean_kernel(const float* __restrict__ xyz, float* __restrict__ meanb)
{
    int b = blockIdx.x, tid = threadIdx.x;
    float sx = 0.f, sy = 0.f, sz = 0.f;
    for (int i = tid; i < 8192; i += 256) {
        const float* q = xyz + ((size_t)b * 8192 + i) * 3;
        sx += q[0]; sy += q[1]; sz += q[2];
    }
    __shared__ float sh[768];
    sh[tid] = sx; sh[256 + tid] = sy; sh[512 + tid] = sz;
    __syncthreads();
    for (int off = 128; off; off >>= 1) {
        if (tid < off) {
            sh[tid]       += sh[tid + off];
            sh[256 + tid] += sh[256 + tid + off];
            sh[512 + tid] += sh[512 + tid + off];
        }
        __syncthreads();
    }
    if (tid == 0) {
        meanb[b * 3 + 0] = sh[0]   / 8192.f;
        meanb[b * 3 + 1] = sh[256] / 8192.f;
        meanb[b * 3 + 2] = sh[512] / 8192.f;
    }
}

// ---------------- farthest point sampling (2 barriers/iter) ------------------
__global__ void __launch_bounds__(1024) fps_kernel(
    const float* __restrict__ xyz, const float* __restrict__ meanb,
    float* __restrict__ nxyz)
{
    const int b = blockIdx.x, tid = threadIdx.x;
    const int lane = tid & 31, wid = tid >> 5;
    const int N1 = 8193;
    float px[9], py[9], pz[9], dist[9];
#pragma unroll
    for (int j = 0; j < 9; ++j) {
        int p = j * 1024 + tid;
        if (p < N1) {
            if (p == 0) {
                px[j] = meanb[b * 3]; py[j] = meanb[b * 3 + 1]; pz[j] = meanb[b * 3 + 2];
            } else {
                const float* q = xyz + ((size_t)b * 8192 + (p - 1)) * 3;
                px[j] = q[0]; py[j] = q[1]; pz[j] = q[2];
            }
        } else { px[j] = 0.f; py[j] = 0.f; pz[j] = 0.f; }
        dist[j] = 1e10f;
    }
    __shared__ float sc[3];
    __shared__ unsigned long long wred[32];
    int far = 0;
    for (int t = 0; t < 1024; ++t) {
        if ((far & 1023) == tid) {
            int j = far >> 10;
            sc[0] = px[j]; sc[1] = py[j]; sc[2] = pz[j];
            float* o = nxyz + ((size_t)b * 1024 + t) * 3;
            o[0] = px[j]; o[1] = py[j]; o[2] = pz[j];
        }
        __syncthreads();
        float cx = sc[0], cy = sc[1], cz = sc[2];
        unsigned long long best = 0;
#pragma unroll
        for (int j = 0; j < 9; ++j) {
            int p = j * 1024 + tid;
            if (p < N1) {
                float dx = px[j] - cx, dy = py[j] - cy, dz = pz[j] - cz;
                float d = __fadd_rn(__fadd_rn(__fmul_rn(dx, dx), __fmul_rn(dy, dy)),
                                    __fmul_rn(dz, dz));
                float nd = fminf(dist[j], d);
                dist[j] = nd;
                unsigned long long pk =
                    ((unsigned long long)__float_as_uint(nd) << 32) |
                    (unsigned long long)(0xFFFFFFFFu - (unsigned)p);
                if (pk > best) best = pk;
            }
        }
#pragma unroll
        for (int off = 16; off; off >>= 1) {
            unsigned long long o2 = __shfl_down_sync(0xFFFFFFFFu, best, off);
            if (o2 > best) best = o2;
        }
        if (lane == 0) wred[wid] = best;
        __syncthreads();
        // every warp reduces the 32 partials (butterfly -> all lanes agree)
        unsigned long long v = wred[lane];
#pragma unroll
        for (int off = 16; off; off >>= 1) {
            unsigned long long o2 = __shfl_xor_sync(0xFFFFFFFFu, v, off);
            if (o2 > v) v = o2;
        }
        far = (int)(0xFFFFFFFFu - (unsigned)(v & 0xFFFFFFFFull));
    }
}

// ---------------- ball query (smem-staged batch xyz) --------------------------
// one block = 32 centroids of one batch; 8 warps x 4 centroids sequential.
__global__ void ball_kernel(const float* __restrict__ xyz,
                            const float* __restrict__ nxyz,
                            int* __restrict__ idx, float r2, int K)
{
    extern __shared__ float sh[];
    float* sx = sh; float* sy = sh + 8192; float* sz = sh + 16384;
    int tid = threadIdx.x;
    int b = blockIdx.x >> 5;
    int sblk = (blockIdx.x & 31) * 32;
    for (int i = tid; i < 8192; i += 256) {
        const float* q = xyz + ((size_t)b * 8192 + i) * 3;
        sx[i] = q[0]; sy[i] = q[1]; sz[i] = q[2];
    }
    __syncthreads();
    int wid = tid >> 5, lane = tid & 31;
    for (int c = wid; c < 32; c += 8) {
        int w = b * 1024 + sblk + c;
        float cx = nxyz[(size_t)w * 3], cy = nxyz[(size_t)w * 3 + 1], cz = nxyz[(size_t)w * 3 + 2];
        int cnt = 0, first = 0;
        int* out = idx + (size_t)w * K;
        for (int base = 0; base < 8192; base += 32) {
            int p = base + lane;
            float dx = sx[p] - cx, dy = sy[p] - cy, dz = sz[p] - cz;
            float d2 = __fadd_rn(__fadd_rn(__fmul_rn(dx, dx), __fmul_rn(dy, dy)),
                                 __fmul_rn(dz, dz));
            bool in = d2 < r2;
            unsigned mask = __ballot_sync(0xFFFFFFFFu, in);
            if (cnt == 0 && mask) first = base + __ffs(mask) - 1;
            if (in) {
                int pos = cnt + __popc(mask & ((1u << lane) - 1u));
                if (pos < K) out[pos] = p;
            }
            cnt += __popc(mask);
            if (cnt >= K) break;
        }
        if (cnt < K) {
            for (int pos = cnt + lane; pos < K; pos += 32) out[pos] = first;
        }
    }
}

// ---------------- gather (featT: contiguous 64-ch reads per point) -----------
__global__ void gather_kernel(const float* __restrict__ xyz,
                              const float* __restrict__ featT,
                              const float* __restrict__ nxyz,
                              const int* __restrict__ idx,
                              float* __restrict__ X0, int K)
{
    size_t M = (size_t)8192 * K;
    size_t m = (size_t)blockIdx.x * 256 + threadIdx.x;
    if (m >= M) return;
    int k = (int)(m % K);
    int bs = (int)(m / K);
    int b = bs >> 10;
    int p = idx[(size_t)bs * K + k];
    const float* pt = xyz + ((size_t)b * 8192 + p) * 3;
    const float* ct = nxyz + (size_t)bs * 3;
    X0[0 * M + m] = pt[0] - ct[0];
    X0[1 * M + m] = pt[1] - ct[1];
    X0[2 * M + m] = pt[2] - ct[2];
    const float* fb = featT + ((size_t)b * 8192 + p) * 64;
#pragma unroll
    for (int c = 0; c < 64; c += 4) {
        float4 v = *(const float4*)(fb + c);
        X0[(size_t)(3 + c)     * M + m] = v.x;
        X0[(size_t)(3 + c + 1) * M + m] = v.y;
        X0[(size_t)(3 + c + 2) * M + m] = v.z;
        X0[(size_t)(3 + c + 3) * M + m] = v.w;
    }
}

// ---------------- pipelined tensor-core GEMM ---------------------------------
#define WP 72
#define XP 264
__global__ void __launch_bounds__(256, 2) gemm_tc2_kernel(
    int O, int I, int Ipad, int M, int K,
    const float* __restrict__ Wg, const float* __restrict__ X,
    float* __restrict__ Y,
    const float* __restrict__ aa, const float* __restrict__ ad,
    float* __restrict__ gsum, float* __restrict__ gsq,
    unsigned* __restrict__ emax, unsigned* __restrict__ emin)
{
    extern __shared__ float sm[];
    float* Wt = sm;
    float* Xt = sm + 2 * 32 * WP;
    float* ssum = sm + 2 * 32 * WP + 2 * 32 * XP;
    float* ssq  = ssum + 64;

    const int tid = threadIdx.x, lane = tid & 31, wid = tid >> 5;
    const int warpO = wid >> 2, warpM = wid & 3;
    const int ob = blockIdx.x * 64, mb = blockIdx.y * 256;
    const int r0 = lane >> 2, kq = lane & 3;
    const int kx = tid >> 6;
    const int c4 = (tid & 63) * 4;
    const int NT = Ipad >> 5;

    if (tid < 64) { ssum[tid] = 0.f; ssq[tid] = 0.f; }

    float acc[2][8][4];
#pragma unroll
    for (int r = 0; r < 2; ++r)
#pragma unroll
        for (int nt = 0; nt < 8; ++nt)
#pragma unroll
            for (int c = 0; c < 4; ++c) acc[r][nt][c] = 0.f;

    float4 xr[8];

    auto ldgX = [&](int t) {
#pragma unroll
        for (int l = 0; l < 8; ++l) {
            int gk = t * 32 + l * 4 + kx;
            if (gk < I) xr[l] = *(const float4*)(X + (size_t)gk * M + mb + c4);
            else        xr[l] = make_float4(0.f, 0.f, 0.f, 0.f);
        }
    };
    auto stsX = [&](int t, int st) {
        float* Xs = Xt + st * (32 * XP);
#pragma unroll
        for (int l = 0; l < 8; ++l) {
            int k = l * 4 + kx;
            float4 v = xr[l];
            if (aa) {
                int gk = t * 32 + k;
                float A_ = aa[gk], D_ = ad[gk];
                v.x = fmaxf(v.x * A_ + D_, 0.f);
                v.y = fmaxf(v.y * A_ + D_, 0.f);
                v.z = fmaxf(v.z * A_ + D_, 0.f);
                v.w = fmaxf(v.w * A_ + D_, 0.f);
            }
            Xs[k * XP + c4 + 0] = to_tf32(v.x);
            Xs[k * XP + c4 + 1] = to_tf32(v.y);
            Xs[k * XP + c4 + 2] = to_tf32(v.z);
            Xs[k * XP + c4 + 3] = to_tf32(v.w);
        }
    };
    auto cpW = [&](int t, int st) {
        float* Ws = Wt + st * (32 * WP);
#pragma unroll
        for (int l = 0; l < 2; ++l) {
            int e = l * 256 + tid;
            int k = e >> 4, o4 = (e & 15) * 4;
            cp16(&Ws[k * WP + o4], Wg + (size_t)(t * 32 + k) * O + ob + o4);
        }
    };

    ldgX(0);
    cpW(0, 0);
    asm volatile("cp.async.commit_group;\n");
    asm volatile("cp.async.wait_group 0;\n");
    stsX(0, 0);
    if (NT > 1) ldgX(1);
    __syncthreads();

    for (int t = 0; t < NT; ++t) {
        int cur = t & 1, nxt = cur ^ 1;
        if (t + 1 < NT) {
            stsX(t + 1, nxt);
            cpW(t + 1, nxt);
            asm volatile("cp.async.commit_group;\n");
        }

        const float* Wc = Wt + cur * (32 * WP);
        const float* Xc = Xt + cur * (32 * XP);
#pragma unroll
        for (int k8 = 0; k8 < 4; ++k8) {
            int kb = k8 * 8;
            uint32_t afr[2][4], bfr[8][2];
#pragma unroll
            for (int r = 0; r < 2; ++r) {
                int o = warpO * 32 + r * 16 + r0;
                afr[r][0] = __float_as_uint(Wc[(kb + kq) * WP + o]);
                afr[r][1] = __float_as_uint(Wc[(kb + kq) * WP + o + 8]);
                afr[r][2] = __float_as_uint(Wc[(kb + kq + 4) * WP + o]);
                afr[r][3] = __float_as_uint(Wc[(kb + kq + 4) * WP + o + 8]);
            }
#pragma unroll
            for (int nt = 0; nt < 8; ++nt) {
                int m = warpM * 64 + nt * 8 + r0;
                bfr[nt][0] = __float_as_uint(Xc[(kb + kq) * XP + m]);
                bfr[nt][1] = __float_as_uint(Xc[(kb + kq + 4) * XP + m]);
            }
#pragma unroll
            for (int r = 0; r < 2; ++r)
#pragma unroll
                for (int nt = 0; nt < 8; ++nt)
                    mma_tf32(acc[r][nt], afr[r], bfr[nt]);
        }
        // X prefetch AFTER the MMA section: xr not live across the MMA loop
        if (t + 2 < NT) ldgX(t + 2);
        if (t + 1 < NT) asm volatile("cp.async.wait_group 0;\n");
        __syncthreads();
    }

    // --- epilogue ---
#pragma unroll
    for (int r = 0; r < 2; ++r) {
#pragma unroll
        for (int half = 0; half < 2; ++half) {
            int ol = warpO * 32 + r * 16 + r0 + half * 8;
            float s = 0.f, q = 0.f;
            if (Y) {
                size_t rowoff = (size_t)(ob + ol) * M + mb + warpM * 64 + kq * 2;
#pragma unroll
                for (int nt = 0; nt < 8; ++nt) {
                    float v0 = acc[r][nt][half * 2 + 0];
                    float v1 = acc[r][nt][half * 2 + 1];
                    *(float2*)(Y + rowoff + nt * 8) = make_float2(v0, v1);
                    s += v0 + v1;
                    q += v0 * v0 + v1 * v1;
                }
            } else {
                int ntg = K >> 3;
                for (int g0 = 0; g0 < 8; g0 += ntg) {
                    float mxv = -3.4e38f, mnv = 3.4e38f;
                    for (int nt = g0; nt < g0 + ntg; ++nt) {
                        float v0 = acc[r][nt][half * 2 + 0];
                        float v1 = acc[r][nt][half * 2 + 1];
                        s += v0 + v1;
                        q += v0 * v0 + v1 * v1;
                        mxv = fmaxf(mxv, fmaxf(v0, v1));
                        mnv = fminf(mnv, fminf(v0, v1));
                    }
                    mxv = fmaxf(mxv, __shfl_xor_sync(0xFFFFFFFFu, mxv, 1));
                    mnv = fminf(mnv, __shfl_xor_sync(0xFFFFFFFFu, mnv, 1));
                    mxv = fmaxf(mxv, __shfl_xor_sync(0xFFFFFFFFu, mxv, 2));
                    mnv = fminf(mnv, __shfl_xor_sync(0xFFFFFFFFu, mnv, 2));
                    if (kq == 0) {
                        int bs = (mb + warpM * 64 + g0 * 8) / K;
                        atomicMax(&emax[(size_t)(ob + ol) * 8192 + bs], encf(mxv));
                        atomicMax(&emin[(size_t)(ob + ol) * 8192 + bs], encf(-mnv));
                    }
                }
            }
            s += __shfl_xor_sync(0xFFFFFFFFu, s, 1);
            q += __shfl_xor_sync(0xFFFFFFFFu, q, 1);
            s += __shfl_xor_sync(0xFFFFFFFFu, s, 2);
            q += __shfl_xor_sync(0xFFFFFFFFu, q, 2);
            if (kq == 0) {
                atomicAdd(&ssum[ol], s);
                atomicAdd(&ssq[ol], q);
            }
        }
    }
    __syncthreads();
    if (tid < 64) {
        atomicAdd(&gsum[ob + tid], ssum[tid]);
        atomicAdd(&gsq[ob + tid], ssq[tid]);
    }
}

// ---------------- BN finalize -------------------------------------------------
__global__ void finalize_kernel(float* __restrict__ sum, float* __restrict__ sq,
                                const float* __restrict__ g, const float* __restrict__ bb,
                                float* __restrict__ aa, float* __restrict__ ad,
                                int O, float invn)
{
    int c = threadIdx.x;
    if (c < O) {
        float m = sum[c] * invn;
        float v = sq[c] * invn - m * m;
        float a = g[c] / sqrtf(v + 1e-5f);
        aa[c] = a;
        ad[c] = bb[c] - m * a;
    }
    if (c < 256) { sum[c] = 0.f; sq[c] = 0.f; }
}

// ---------------- final: decode max/min, apply last affine+relu --------------
__global__ void maxfin_kernel(const unsigned* __restrict__ emax,
                              const unsigned* __restrict__ emin,
                              const float* __restrict__ aa, const float* __restrict__ ad,
                              float* __restrict__ out, int O, int coff)
{
    int gid = blockIdx.x * blockDim.x + threadIdx.x;
    int total = 8 * O * 1024;
    if (gid >= total) return;
    int s = gid & 1023;
    int c = (gid >> 10) % O;
    int b = gid / (O * 1024);
    int bs = b * 1024 + s;
    float a = aa[c], d = ad[c];
    float y = (a >= 0.f) ? decf(emax[(size_t)c * 8192 + bs])
                         : -decf(emin[(size_t)c * 8192 + bs]);
    out[((size_t)b * 384 + coff + c) * 1024 + s] = fmaxf(y * a + d, 0.f);
}

// ---------------- host launch ------------------------------------------------
extern "C" void kernel_launch(void* const* d_in, const int* in_sizes, int n_in,
                              void* d_out, int out_size)
{
    (void)in_sizes; (void)n_in; (void)out_size;
    const float* xyz  = (const float*)d_in[0];
    const float* feat = (const float*)d_in[1];
    const float* W[2][3]; const float* G[2][3]; const float* Bb[2][3];
    for (int bi = 0; bi < 2; ++bi)
        for (int li = 0; li < 3; ++li) {
            W[bi][li]  = (const float*)d_in[2 + bi * 9 + li * 3 + 0];
            G[bi][li]  = (const float*)d_in[2 + bi * 9 + li * 3 + 1];
            Bb[bi][li] = (const float*)d_in[2 + bi * 9 + li * 3 + 2];
        }
    float* out      = (float*)d_out;
    float* nxyz     = out;            // (8,1024,3)
    float* feat_out = out + 24576;    // (8,384,1024)

    float *bufA, *bufB, *featT, *meanb, *sum, *sq, *aa, *ad, *wt; int* idxb;
    unsigned *emax, *emin;
    cudaGetSymbolAddress((void**)&bufA, g_bufA);
    cudaGetSymbolAddress((void**)&bufB, g_bufB);
    cudaGetSymbolAddress((void**)&featT, g_featT);
    cudaGetSymbolAddress((void**)&meanb, g_meanb);
    cudaGetSymbolAddress((void**)&idxb, g_idxb);
    cudaGetSymbolAddress((void**)&sum, g_sum);
    cudaGetSymbolAddress((void**)&sq, g_sq);
    cudaGetSymbolAddress((void**)&aa, g_affa);
    cudaGetSymbolAddress((void**)&ad, g_affd);
    cudaGetSymbolAddress((void**)&wt, g_wt);
    cudaGetSymbolAddress((void**)&emax, g_emax);
    cudaGetSymbolAddress((void**)&emin, g_emin);

    const int SMEM_GEMM = (2 * 32 * WP + 2 * 32 * XP + 128) * 4;  // 86528 B
    cudaFuncSetAttribute(gemm_tc2_kernel,
                         cudaFuncAttributeMaxDynamicSharedMemorySize, SMEM_GEMM);
    const int SMEM_BALL = 3 * 8192 * 4;                           // 98304 B
    cudaFuncSetAttribute(ball_kernel,
                         cudaFuncAttributeMaxDynamicSharedMemorySize, SMEM_BALL);

    const int OS[2][4] = { {67, 64, 64, 128}, {67, 64, 128, 256} };
    const int KS[2] = {32, 64};
    const float R2[2] = { (float)(0.4 * 0.4), (float)(0.8 * 0.8) };
    const int IP[2][3]   = { {96, 64, 64}, {96, 64, 128} };
    const int WOFF[2][3] = { {0, 6144, 10240}, {18432, 24576, 32768} };

    // launch 0: all prep (weights + transpose + stats zero)
    prep_kernel<<<4352, 256>>>(W[0][0], W[0][1], W[0][2], W[1][0], W[1][1], W[1][2],
                               feat, wt, featT, sum, sq);
    // launch 1-2
    mean_kernel<<<8, 256>>>(xyz, meanb);
    fps_kernel<<<8, 1024>>>(xyz, meanb, nxyz);

    for (int bi = 0; bi < 2; ++bi) {
        int K = KS[bi];
        int M = 8192 * K;
        float invn = 1.0f / (float)M;

        ball_kernel<<<256, 256, SMEM_BALL>>>(xyz, nxyz, idxb, R2[bi], K);
        gather_kernel<<<(M + 255) / 256, 256>>>(xyz, featT, nxyz, idxb, bufA, K);

        // L0: (O1 x 67) * X0 -> bufB      (launch index 5 on bi==0 -> ncu target)
        {
            dim3 grid(OS[bi][1] / 64, M / 256);
            gemm_tc2_kernel<<<grid, 256, SMEM_GEMM>>>(
                OS[bi][1], OS[bi][0], IP[bi][0], M, K, wt + WOFF[bi][0],
                bufA, bufB, nullptr, nullptr, sum, sq, nullptr, nullptr);
            finalize_kernel<<<1, 256>>>(sum, sq, G[bi][0], Bb[bi][0], aa, ad, OS[bi][1], invn);
        }
        // L1: (O2 x O1) * act(bufB) -> bufA
        {
            dim3 grid(OS[bi][2] / 64, M / 256);
            gemm_tc2_kernel<<<grid, 256, SMEM_GEMM>>>(
                OS[bi][2], OS[bi][1], IP[bi][1], M, K, wt + WOFF[bi][1],
                bufB, bufA, aa, ad, sum, sq, nullptr, nullptr);
            finalize_kernel<<<1, 256>>>(sum, sq, G[bi][1], Bb[bi][1], aa, ad, OS[bi][2], invn);
        }
        // L2: (O3 x O2) * act(bufA) -> fused max/min epilogue (no Y write)
        {
            cudaMemsetAsync(emax, 0, (size_t)OS[bi][3] * 8192 * 4, 0);
            cudaMemsetAsync(emin, 0, (size_t)OS[bi][3] * 8192 * 4, 0);
            dim3 grid(OS[bi][3] / 64, M / 256);
            gemm_tc2_kernel<<<grid, 256, SMEM_GEMM>>>(
                OS[bi][3], OS[bi][2], IP[bi][2], M, K, wt + WOFF[bi][2],
                bufA, nullptr, aa, ad, sum, sq, emax, emin);
            finalize_kernel<<<1, 256>>>(sum, sq, G[bi][2], Bb[bi][2], aa, ad, OS[bi][3], invn);
        }
        // decode + final affine + relu -> output
        {
            int total = 8 * OS[bi][3] * 1024;
            maxfin_kernel<<<(total + 255) / 256, 256>>>(emax, emin, aa, ad, feat_out,
                                                        OS[bi][3], bi == 0 ? 0 : 128);
        }
    }
}

// round 11
// speedup vs baseline: 1.0453x; 1.0453x over previous
#include <cuda_runtime.h>
#include <cstdint>
#include <cstddef>

// ---------------- scratch (static device memory; no allocs allowed) ----------
static __device__ float g_bufA[(size_t)128 * 524288];   // 256 MB
static __device__ float g_bufB[(size_t)128 * 524288];   // 256 MB
static __device__ float g_featT[(size_t)8 * 8192 * 64]; // 16 MB transposed features
static __device__ float g_meanb[24];
static __device__ int   g_idxb[8 * 1024 * 64];
static __device__ float g_sum[256];
static __device__ float g_sq[256];
static __device__ float g_affa[256];
static __device__ float g_affd[256];
static __device__ float g_wt[65536];                    // pre-transposed tf32 weights
static __device__ unsigned g_emax[256 * 8192];          // encoded max
static __device__ unsigned g_emin[256 * 8192];          // encoded max of -y

// ---------------- helpers ----------------------------------------------------
__device__ __forceinline__ float to_tf32(float x)
{
    uint32_t r;
    asm volatile("cvt.rna.tf32.f32 %0, %1;\n" : "=r"(r) : "f"(x));
    return __uint_as_float(r);
}
__device__ __forceinline__ void mma_tf32(float* d, const uint32_t* a, const uint32_t* b)
{
    asm volatile(
        "mma.sync.aligned.m16n8k8.row.col.f32.tf32.tf32.f32 "
        "{%0,%1,%2,%3}, {%4,%5,%6,%7}, {%8,%9}, {%0,%1,%2,%3};\n"
        : "+f"(d[0]), "+f"(d[1]), "+f"(d[2]), "+f"(d[3])
        : "r"(a[0]), "r"(a[1]), "r"(a[2]), "r"(a[3]),
          "r"(b[0]), "r"(b[1]));
}
__device__ __forceinline__ void cp16(void* dst, const void* src)
{
    uint32_t d = (uint32_t)__cvta_generic_to_shared(dst);
    asm volatile("cp.async.ca.shared.global [%0], [%1], 16;\n" :: "r"(d), "l"(src));
}
__device__ __forceinline__ unsigned encf(float f)
{
    unsigned u = __float_as_uint(f);
    return (u >> 31) ? ~u : (u | 0x80000000u);
}
__device__ __forceinline__ float decf(unsigned u)
{
    return __uint_as_float((u >> 31) ? (u & 0x7FFFFFFFu) : ~u);
}

// ---------------- prep: all weight transposes + feat transpose + stat zero ---
__global__ void prep_kernel(const float* __restrict__ w0, const float* __restrict__ w1,
                            const float* __restrict__ w2, const float* __restrict__ w3,
                            const float* __restrict__ w4, const float* __restrict__ w5,
                            const float* __restrict__ feat,
                            float* __restrict__ wt, float* __restrict__ featT,
                            float* __restrict__ sum, float* __restrict__ sq)
{
    int blk = blockIdx.x, tid = threadIdx.x;
    if (blk == 0) { sum[tid] = 0.f; sq[tid] = 0.f; }
    if (blk < 256) {
        const int lo[6]   = {0, 24, 40, 72, 96, 128};
        const int Os[6]   = {64, 64, 128, 64, 128, 256};
        const int Is[6]   = {67, 64, 64, 67, 64, 128};
        const int Ip[6]   = {96, 64, 64, 96, 64, 128};
        const int woff[6] = {0, 6144, 10240, 18432, 24576, 32768};
        const float* Ws[6] = {w0, w1, w2, w3, w4, w5};
        int li = 5;
#pragma unroll
        for (int i = 1; i < 6; ++i) if (blk < lo[i]) { li = i - 1; break; }
        int e = (blk - lo[li]) * 256 + tid;
        int O = Os[li], I = Is[li], Ipad = Ip[li];
        if (e < Ipad * O) {
            int k = e / O, o = e % O;
            wt[woff[li] + e] = (k < I) ? to_tf32(Ws[li][(size_t)o * I + k]) : 0.f;
        }
    } else {
        __shared__ float tile[32][33];
        int t = blk - 256;
        int b = t >> 9;
        int rem = t & 511;
        int c0 = (rem >> 8) * 32;
        int p0 = (rem & 255) * 32;
        int tx = tid & 31, ty = tid >> 5;
#pragma unroll
        for (int i = ty; i < 32; i += 8)
            tile[i][tx] = feat[((size_t)b * 64 + c0 + i) * 8192 + p0 + tx];
        __syncthreads();
#pragma unroll
        for (int i = ty; i < 32; i += 8)
            featT[((size_t)b * 8192 + p0 + i) * 64 + c0 + tx] = tile[tx][i];
    }
}

// ---------------- mean over N of xyz ----------------------------------------
__global__ void mean_kernel(const float* __restrict__ xyz, float* __restrict__ meanb)
{
    int b = blockIdx.x, tid = threadIdx.x;
    float sx = 0.f, sy = 0.f, sz = 0.f;
    for (int i = tid; i < 8192; i += 256) {
        const float* q = xyz + ((size_t)b * 8192 + i) * 3;
        sx += q[0]; sy += q[1]; sz += q[2];
    }
    __shared__ float sh[768];
    sh[tid] = sx; sh[256 + tid] = sy; sh[512 + tid] = sz;
    __syncthreads();
    for (int off = 128; off; off >>= 1) {
        if (tid < off) {
            sh[tid]       += sh[tid + off];
            sh[256 + tid] += sh[256 + tid + off];
            sh[512 + tid] += sh[512 + tid + off];
        }
        __syncthreads();
    }
    if (tid == 0) {
        meanb[b * 3 + 0] = sh[0]   / 8192.f;
        meanb[b * 3 + 1] = sh[256] / 8192.f;
        meanb[b * 3 + 2] = sh[512] / 8192.f;
    }
}

// ---------------- farthest point sampling ------------------------------------
// per-point tracking in float (bestv) + index (bestj); u64 pack at reduce only
__global__ void __launch_bounds__(1024) fps_kernel(
    const float* __restrict__ xyz, const float* __restrict__ meanb,
    float* __restrict__ nxyz)
{
    const int b = blockIdx.x, tid = threadIdx.x;
    const int lane = tid & 31, wid = tid >> 5;
    const int N1 = 8193;
    float px[9], py[9], pz[9], dist[9];
#pragma unroll
    for (int j = 0; j < 9; ++j) {
        int p = j * 1024 + tid;
        if (p < N1) {
            if (p == 0) {
                px[j] = meanb[b * 3]; py[j] = meanb[b * 3 + 1]; pz[j] = meanb[b * 3 + 2];
            } else {
                const float* q = xyz + ((size_t)b * 8192 + (p - 1)) * 3;
                px[j] = q[0]; py[j] = q[1]; pz[j] = q[2];
            }
        } else { px[j] = 0.f; py[j] = 0.f; pz[j] = 0.f; }
        dist[j] = 1e10f;
    }
    __shared__ float sc[3];
    __shared__ unsigned long long wred[32];
    int far = 0;
    const bool has9 = (tid == 0);   // only p=8192 valid in j=8
    for (int t = 0; t < 1024; ++t) {
        if ((far & 1023) == tid) {
            int j = far >> 10;
            sc[0] = px[j]; sc[1] = py[j]; sc[2] = pz[j];
            float* o = nxyz + ((size_t)b * 1024 + t) * 3;
            o[0] = px[j]; o[1] = py[j]; o[2] = pz[j];
        }
        __syncthreads();
        float cx = sc[0], cy = sc[1], cz = sc[2];
        float bestv = -1.f;
        int bestj = 0;
#pragma unroll
        for (int j = 0; j < 8; ++j) {
            float dx = px[j] - cx, dy = py[j] - cy, dz = pz[j] - cz;
            float d = __fadd_rn(__fadd_rn(__fmul_rn(dx, dx), __fmul_rn(dy, dy)),
                                __fmul_rn(dz, dz));
            float nd = fminf(dist[j], d);
            dist[j] = nd;
            if (nd > bestv) { bestv = nd; bestj = j; }   // strict > : first index wins
        }
        if (has9) {
            float dx = px[8] - cx, dy = py[8] - cy, dz = pz[8] - cz;
            float d = __fadd_rn(__fadd_rn(__fmul_rn(dx, dx), __fmul_rn(dy, dy)),
                                __fmul_rn(dz, dz));
            float nd = fminf(dist[8], d);
            dist[8] = nd;
            if (nd > bestv) { bestv = nd; bestj = 8; }
        }
        unsigned bp = (unsigned)(bestj * 1024 + tid);
        unsigned long long best =
            ((unsigned long long)__float_as_uint(bestv) << 32) |
            (unsigned long long)(0xFFFFFFFFu - bp);
#pragma unroll
        for (int off = 16; off; off >>= 1) {
            unsigned long long o2 = __shfl_down_sync(0xFFFFFFFFu, best, off);
            if (o2 > best) best = o2;
        }
        if (lane == 0) wred[wid] = best;
        __syncthreads();
        unsigned long long v = wred[lane];
#pragma unroll
        for (int off = 16; off; off >>= 1) {
            unsigned long long o2 = __shfl_xor_sync(0xFFFFFFFFu, v, off);
            if (o2 > v) v = o2;
        }
        far = (int)(0xFFFFFFFFu - (unsigned)(v & 0xFFFFFFFFull));
    }
}

// ---------------- ball query: 1 centroid per warp, smem-staged xyz ------------
__global__ void __launch_bounds__(1024) ball_kernel(
    const float* __restrict__ xyz, const float* __restrict__ nxyz,
    int* __restrict__ idx, float r2, int K)
{
    extern __shared__ float sh[];
    float* sx = sh; float* sy = sh + 8192; float* sz = sh + 16384;
    int tid = threadIdx.x;
    int b = blockIdx.x >> 5;
    int sblk = (blockIdx.x & 31) * 32;
    for (int i = tid; i < 8192; i += 1024) {
        const float* q = xyz + ((size_t)b * 8192 + i) * 3;
        sx[i] = q[0]; sy[i] = q[1]; sz[i] = q[2];
    }
    __syncthreads();
    int wid = tid >> 5, lane = tid & 31;
    int w = b * 1024 + sblk + wid;          // one centroid per warp
    float cx = nxyz[(size_t)w * 3], cy = nxyz[(size_t)w * 3 + 1], cz = nxyz[(size_t)w * 3 + 2];
    int cnt = 0, first = 0;
    int* out = idx + (size_t)w * K;
    for (int base = 0; base < 8192; base += 32) {
        int p = base + lane;
        float dx = sx[p] - cx, dy = sy[p] - cy, dz = sz[p] - cz;
        float d2 = __fadd_rn(__fadd_rn(__fmul_rn(dx, dx), __fmul_rn(dy, dy)),
                             __fmul_rn(dz, dz));
        bool in = d2 < r2;
        unsigned mask = __ballot_sync(0xFFFFFFFFu, in);
        if (cnt == 0 && mask) first = base + __ffs(mask) - 1;
        if (in) {
            int pos = cnt + __popc(mask & ((1u << lane) - 1u));
            if (pos < K) out[pos] = p;
        }
        cnt += __popc(mask);
        if (cnt >= K) break;
    }
    if (cnt < K) {
        for (int pos = cnt + lane; pos < K; pos += 32) out[pos] = first;
    }
}

// ---------------- gather (featT: contiguous 64-ch reads per point) -----------
__global__ void gather_kernel(const float* __restrict__ xyz,
                              const float* __restrict__ featT,
                              const float* __restrict__ nxyz,
                              const int* __restrict__ idx,
                              float* __restrict__ X0, int K)
{
    size_t M = (size_t)8192 * K;
    size_t m = (size_t)blockIdx.x * 256 + threadIdx.x;
    if (m >= M) return;
    int k = (int)(m % K);
    int bs = (int)(m / K);
    int b = bs >> 10;
    int p = idx[(size_t)bs * K + k];
    const float* pt = xyz + ((size_t)b * 8192 + p) * 3;
    const float* ct = nxyz + (size_t)bs * 3;
    X0[0 * M + m] = pt[0] - ct[0];
    X0[1 * M + m] = pt[1] - ct[1];
    X0[2 * M + m] = pt[2] - ct[2];
    const float* fb = featT + ((size_t)b * 8192 + p) * 64;
#pragma unroll
    for (int c = 0; c < 64; c += 4) {
        float4 v = *(const float4*)(fb + c);
        X0[(size_t)(3 + c)     * M + m] = v.x;
        X0[(size_t)(3 + c + 1) * M + m] = v.y;
        X0[(size_t)(3 + c + 2) * M + m] = v.z;
        X0[(size_t)(3 + c + 3) * M + m] = v.w;
    }
}

// ---------------- pipelined tensor-core GEMM (R7 ordering) --------------------
#define WP 72
#define XP 264
__global__ void __launch_bounds__(256, 2) gemm_tc2_kernel(
    int O, int I, int Ipad, int M, int K,
    const float* __restrict__ Wg, const float* __restrict__ X,
    float* __restrict__ Y,
    const float* __restrict__ aa, const float* __restrict__ ad,
    float* __restrict__ gsum, float* __restrict__ gsq,
    unsigned* __restrict__ emax, unsigned* __restrict__ emin)
{
    extern __shared__ float sm[];
    float* Wt = sm;
    float* Xt = sm + 2 * 32 * WP;
    float* ssum = sm + 2 * 32 * WP + 2 * 32 * XP;
    float* ssq  = ssum + 64;

    const int tid = threadIdx.x, lane = tid & 31, wid = tid >> 5;
    const int warpO = wid >> 2, warpM = wid & 3;
    const int ob = blockIdx.x * 64, mb = blockIdx.y * 256;
    const int r0 = lane >> 2, kq = lane & 3;
    const int kx = tid >> 6;
    const int c4 = (tid & 63) * 4;
    const int NT = Ipad >> 5;

    if (tid < 64) { ssum[tid] = 0.f; ssq[tid] = 0.f; }

    float acc[2][8][4];
#pragma unroll
    for (int r = 0; r < 2; ++r)
#pragma unroll
        for (int nt = 0; nt < 8; ++nt)
#pragma unroll
            for (int c = 0; c < 4; ++c) acc[r][nt][c] = 0.f;

    float4 xr[8];

    auto ldgX = [&](int t) {
#pragma unroll
        for (int l = 0; l < 8; ++l) {
            int gk = t * 32 + l * 4 + kx;
            if (gk < I) xr[l] = *(const float4*)(X + (size_t)gk * M + mb + c4);
            else        xr[l] = make_float4(0.f, 0.f, 0.f, 0.f);
        }
    };
    auto stsX = [&](int t, int st) {
        float* Xs = Xt + st * (32 * XP);
#pragma unroll
        for (int l = 0; l < 8; ++l) {
            int k = l * 4 + kx;
            float4 v = xr[l];
            if (aa) {
                int gk = t * 32 + k;
                float A_ = aa[gk], D_ = ad[gk];
                v.x = fmaxf(v.x * A_ + D_, 0.f);
                v.y = fmaxf(v.y * A_ + D_, 0.f);
                v.z = fmaxf(v.z * A_ + D_, 0.f);
                v.w = fmaxf(v.w * A_ + D_, 0.f);
            }
            Xs[k * XP + c4 + 0] = to_tf32(v.x);
            Xs[k * XP + c4 + 1] = to_tf32(v.y);
            Xs[k * XP + c4 + 2] = to_tf32(v.z);
            Xs[k * XP + c4 + 3] = to_tf32(v.w);
        }
    };
    auto cpW = [&](int t, int st) {
        float* Ws = Wt + st * (32 * WP);
#pragma unroll
        for (int l = 0; l < 2; ++l) {
            int e = l * 256 + tid;
            int k = e >> 4, o4 = (e & 15) * 4;
            cp16(&Ws[k * WP + o4], Wg + (size_t)(t * 32 + k) * O + ob + o4);
        }
    };

    ldgX(0);
    cpW(0, 0);
    asm volatile("cp.async.commit_group;\n");
    asm volatile("cp.async.wait_group 0;\n");
    stsX(0, 0);
    if (NT > 1) ldgX(1);
    __syncthreads();

    for (int t = 0; t < NT; ++t) {
        int cur = t & 1, nxt = cur ^ 1;
        if (t + 1 < NT) {
            stsX(t + 1, nxt);
            cpW(t + 1, nxt);
            asm volatile("cp.async.commit_group;\n");
        }
        if (t + 2 < NT) ldgX(t + 2);

        const float* Wc = Wt + cur * (32 * WP);
        const float* Xc = Xt + cur * (32 * XP);
#pragma unroll
        for (int k8 = 0; k8 < 4; ++k8) {
            int kb = k8 * 8;
            uint32_t afr[2][4], bfr[8][2];
#pragma unroll
            for (int r = 0; r < 2; ++r) {
                int o = warpO * 32 + r * 16 + r0;
                afr[r][0] = __float_as_uint(Wc[(kb + kq) * WP + o]);
                afr[r][1] = __float_as_uint(Wc[(kb + kq) * WP + o + 8]);
                afr[r][2] = __float_as_uint(Wc[(kb + kq + 4) * WP + o]);
                afr[r][3] = __float_as_uint(Wc[(kb + kq + 4) * WP + o + 8]);
            }
#pragma unroll
            for (int nt = 0; nt < 8; ++nt) {
                int m = warpM * 64 + nt * 8 + r0;
                bfr[nt][0] = __float_as_uint(Xc[(kb + kq) * XP + m]);
                bfr[nt][1] = __float_as_uint(Xc[(kb + kq + 4) * XP + m]);
            }
#pragma unroll
            for (int r = 0; r < 2; ++r)
#pragma unroll
                for (int nt = 0; nt < 8; ++nt)
                    mma_tf32(acc[r][nt], afr[r], bfr[nt]);
        }
        if (t + 1 < NT) asm volatile("cp.async.wait_group 0;\n");
        __syncthreads();
    }

    // --- epilogue ---
#pragma unroll
    for (int r = 0; r < 2; ++r) {
#pragma unroll
        for (int half = 0; half < 2; ++half) {
            int ol = warpO * 32 + r * 16 + r0 + half * 8;
            float s = 0.f, q = 0.f;
            if (Y) {
                size_t rowoff = (size_t)(ob + ol) * M + mb + warpM * 64 + kq * 2;
#pragma unroll
                for (int nt = 0; nt < 8; ++nt) {
                    float v0 = acc[r][nt][half * 2 + 0];
                    float v1 = acc[r][nt][half * 2 + 1];
                    *(float2*)(Y + rowoff + nt * 8) = make_float2(v0, v1);
                    s += v0 + v1;
                    q += v0 * v0 + v1 * v1;
                }
            } else {
                int ntg = K >> 3;
                for (int g0 = 0; g0 < 8; g0 += ntg) {
                    float mxv = -3.4e38f, mnv = 3.4e38f;
                    for (int nt = g0; nt < g0 + ntg; ++nt) {
                        float v0 = acc[r][nt][half * 2 + 0];
                        float v1 = acc[r][nt][half * 2 + 1];
                        s += v0 + v1;
                        q += v0 * v0 + v1 * v1;
                        mxv = fmaxf(mxv, fmaxf(v0, v1));
                        mnv = fminf(mnv, fminf(v0, v1));
                    }
                    mxv = fmaxf(mxv, __shfl_xor_sync(0xFFFFFFFFu, mxv, 1));
                    mnv = fminf(mnv, __shfl_xor_sync(0xFFFFFFFFu, mnv, 1));
                    mxv = fmaxf(mxv, __shfl_xor_sync(0xFFFFFFFFu, mxv, 2));
                    mnv = fminf(mnv, __shfl_xor_sync(0xFFFFFFFFu, mnv, 2));
                    if (kq == 0) {
                        int bs = (mb + warpM * 64 + g0 * 8) / K;
                        atomicMax(&emax[(size_t)(ob + ol) * 8192 + bs], encf(mxv));
                        atomicMax(&emin[(size_t)(ob + ol) * 8192 + bs], encf(-mnv));
                    }
                }
            }
            s += __shfl_xor_sync(0xFFFFFFFFu, s, 1);
            q += __shfl_xor_sync(0xFFFFFFFFu, q, 1);
            s += __shfl_xor_sync(0xFFFFFFFFu, s, 2);
            q += __shfl_xor_sync(0xFFFFFFFFu, q, 2);
            if (kq == 0) {
                atomicAdd(&ssum[ol], s);
                atomicAdd(&ssq[ol], q);
            }
        }
    }
    __syncthreads();
    if (tid < 64) {
        atomicAdd(&gsum[ob + tid], ssum[tid]);
        atomicAdd(&gsq[ob + tid], ssq[tid]);
    }
}

// ---------------- BN finalize -------------------------------------------------
__global__ void finalize_kernel(float* __restrict__ sum, float* __restrict__ sq,
                                const float* __restrict__ g, const float* __restrict__ bb,
                                float* __restrict__ aa, float* __restrict__ ad,
                                int O, float invn)
{
    int c = threadIdx.x;
    if (c < O) {
        float m = sum[c] * invn;
        float v = sq[c] * invn - m * m;
        float a = g[c] / sqrtf(v + 1e-5f);
        aa[c] = a;
        ad[c] = bb[c] - m * a;
    }
    if (c < 256) { sum[c] = 0.f; sq[c] = 0.f; }
}

// ---------------- final: decode max/min, apply last affine+relu --------------
__global__ void maxfin_kernel(const unsigned* __restrict__ emax,
                              const unsigned* __restrict__ emin,
                              const float* __restrict__ aa, const float* __restrict__ ad,
                              float* __restrict__ out, int O, int coff)
{
    int gid = blockIdx.x * blockDim.x + threadIdx.x;
    int total = 8 * O * 1024;
    if (gid >= total) return;
    int s = gid & 1023;
    int c = (gid >> 10) % O;
    int b = gid / (O * 1024);
    int bs = b * 1024 + s;
    float a = aa[c], d = ad[c];
    float y = (a >= 0.f) ? decf(emax[(size_t)c * 8192 + bs])
                         : -decf(emin[(size_t)c * 8192 + bs]);
    out[((size_t)b * 384 + coff + c) * 1024 + s] = fmaxf(y * a + d, 0.f);
}

// ---------------- host launch ------------------------------------------------
extern "C" void kernel_launch(void* const* d_in, const int* in_sizes, int n_in,
                              void* d_out, int out_size)
{
    (void)in_sizes; (void)n_in; (void)out_size;
    const float* xyz  = (const float*)d_in[0];
    const float* feat = (const float*)d_in[1];
    const float* W[2][3]; const float* G[2][3]; const float* Bb[2][3];
    for (int bi = 0; bi < 2; ++bi)
        for (int li = 0; li < 3; ++li) {
            W[bi][li]  = (const float*)d_in[2 + bi * 9 + li * 3 + 0];
            G[bi][li]  = (const float*)d_in[2 + bi * 9 + li * 3 + 1];
            Bb[bi][li] = (const float*)d_in[2 + bi * 9 + li * 3 + 2];
        }
    float* out      = (float*)d_out;
    float* nxyz     = out;            // (8,1024,3)
    float* feat_out = out + 24576;    // (8,384,1024)

    float *bufA, *bufB, *featT, *meanb, *sum, *sq, *aa, *ad, *wt; int* idxb;
    unsigned *emax, *emin;
    cudaGetSymbolAddress((void**)&bufA, g_bufA);
    cudaGetSymbolAddress((void**)&bufB, g_bufB);
    cudaGetSymbolAddress((void**)&featT, g_featT);
    cudaGetSymbolAddress((void**)&meanb, g_meanb);
    cudaGetSymbolAddress((void**)&idxb, g_idxb);
    cudaGetSymbolAddress((void**)&sum, g_sum);
    cudaGetSymbolAddress((void**)&sq, g_sq);
    cudaGetSymbolAddress((void**)&aa, g_affa);
    cudaGetSymbolAddress((void**)&ad, g_affd);
    cudaGetSymbolAddress((void**)&wt, g_wt);
    cudaGetSymbolAddress((void**)&emax, g_emax);
    cudaGetSymbolAddress((void**)&emin, g_emin);

    const int SMEM_GEMM = (2 * 32 * WP + 2 * 32 * XP + 128) * 4;  // 86528 B
    cudaFuncSetAttribute(gemm_tc2_kernel,
                         cudaFuncAttributeMaxDynamicSharedMemorySize, SMEM_GEMM);
    const int SMEM_BALL = 3 * 8192 * 4;                           // 98304 B
    cudaFuncSetAttribute(ball_kernel,
                         cudaFuncAttributeMaxDynamicSharedMemorySize, SMEM_BALL);

    const int OS[2][4] = { {67, 64, 64, 128}, {67, 64, 128, 256} };
    const int KS[2] = {32, 64};
    const float R2[2] = { (float)(0.4 * 0.4), (float)(0.8 * 0.8) };
    const int IP[2][3]   = { {96, 64, 64}, {96, 64, 128} };
    const int WOFF[2][3] = { {0, 6144, 10240}, {18432, 24576, 32768} };

    prep_kernel<<<4352, 256>>>(W[0][0], W[0][1], W[0][2], W[1][0], W[1][1], W[1][2],
                               feat, wt, featT, sum, sq);
    mean_kernel<<<8, 256>>>(xyz, meanb);
    fps_kernel<<<8, 1024>>>(xyz, meanb, nxyz);

    for (int bi = 0; bi < 2; ++bi) {
        int K = KS[bi];
        int M = 8192 * K;
        float invn = 1.0f / (float)M;

        ball_kernel<<<256, 1024, SMEM_BALL>>>(xyz, nxyz, idxb, R2[bi], K);
        gather_kernel<<<(M + 255) / 256, 256>>>(xyz, featT, nxyz, idxb, bufA, K);

        // L0: (O1 x 67) * X0 -> bufB
        {
            dim3 grid(OS[bi][1] / 64, M / 256);
            gemm_tc2_kernel<<<grid, 256, SMEM_GEMM>>>(
                OS[bi][1], OS[bi][0], IP[bi][0], M, K, wt + WOFF[bi][0],
                bufA, bufB, nullptr, nullptr, sum, sq, nullptr, nullptr);
            finalize_kernel<<<1, 256>>>(sum, sq, G[bi][0], Bb[bi][0], aa, ad, OS[bi][1], invn);
        }
        // L1: (O2 x O1) * act(bufB) -> bufA
        {
            dim3 grid(OS[bi][2] / 64, M / 256);
            gemm_tc2_kernel<<<grid, 256, SMEM_GEMM>>>(
                OS[bi][2], OS[bi][1], IP[bi][1], M, K, wt + WOFF[bi][1],
                bufB, bufA, aa, ad, sum, sq, nullptr, nullptr);
            finalize_kernel<<<1, 256>>>(sum, sq, G[bi][1], Bb[bi][1], aa, ad, OS[bi][2], invn);
        }
        // L2: (O3 x O2) * act(bufA) -> fused max/min epilogue (no Y write)
        {
            cudaMemsetAsync(emax, 0, (size_t)OS[bi][3] * 8192 * 4, 0);
            cudaMemsetAsync(emin, 0, (size_t)OS[bi][3] * 8192 * 4, 0);
            dim3 grid(OS[bi][3] / 64, M / 256);
            gemm_tc2_kernel<<<grid, 256, SMEM_GEMM>>>(
                OS[bi][3], OS[bi][2], IP[bi][2], M, K, wt + WOFF[bi][2],
                bufA, nullptr, aa, ad, sum, sq, emax, emin);
            finalize_kernel<<<1, 256>>>(sum, sq, G[bi][2], Bb[bi][2], aa, ad, OS[bi][3], invn);
        }
        // decode + final affine + relu -> output
        {
            int total = 8 * OS[bi][3] * 1024;
            maxfin_kernel<<<(total + 255) / 256, 256>>>(emax, emin, aa, ad, feat_out,
                                                        OS[bi][3], bi == 0 ? 0 : 128);
        }
    }
}

// round 12
// speedup vs baseline: 1.0544x; 1.0086x over previous
#include <cuda_runtime.h>
#include <cstdint>
#include <cstddef>

// ---------------- scratch (static device memory; no allocs allowed) ----------
static __device__ float g_bufA[(size_t)128 * 524288];   // 256 MB
static __device__ float g_bufB[(size_t)128 * 524288];   // 256 MB
static __device__ float g_featT[(size_t)8 * 8192 * 64]; // 16 MB transposed features
static __device__ float g_meanb[24];
static __device__ int   g_idxb[8 * 1024 * 64];
static __device__ float g_sum[256];
static __device__ float g_sq[256];
static __device__ float g_affa[256];
static __device__ float g_affd[256];
static __device__ float g_wt[65536];                    // pre-transposed tf32 weights
static __device__ unsigned g_emax[256 * 8192];          // encoded max
static __device__ unsigned g_emin[256 * 8192];          // encoded max of -y

// ---------------- helpers ----------------------------------------------------
__device__ __forceinline__ float to_tf32(float x)
{
    uint32_t r;
    asm volatile("cvt.rna.tf32.f32 %0, %1;\n" : "=r"(r) : "f"(x));
    return __uint_as_float(r);
}
__device__ __forceinline__ void mma_tf32(float* d, const uint32_t* a, const uint32_t* b)
{
    asm volatile(
        "mma.sync.aligned.m16n8k8.row.col.f32.tf32.tf32.f32 "
        "{%0,%1,%2,%3}, {%4,%5,%6,%7}, {%8,%9}, {%0,%1,%2,%3};\n"
        : "+f"(d[0]), "+f"(d[1]), "+f"(d[2]), "+f"(d[3])
        : "r"(a[0]), "r"(a[1]), "r"(a[2]), "r"(a[3]),
          "r"(b[0]), "r"(b[1]));
}
__device__ __forceinline__ void cp16(void* dst, const void* src)
{
    uint32_t d = (uint32_t)__cvta_generic_to_shared(dst);
    asm volatile("cp.async.ca.shared.global [%0], [%1], 16;\n" :: "r"(d), "l"(src));
}
__device__ __forceinline__ unsigned encf(float f)
{
    unsigned u = __float_as_uint(f);
    return (u >> 31) ? ~u : (u | 0x80000000u);
}
__device__ __forceinline__ float decf(unsigned u)
{
    return __uint_as_float((u >> 31) ? (u & 0x7FFFFFFFu) : ~u);
}

// ---------------- prep: weights (permuted for L0) + feat transpose + zeroing -
// blocks [0,256): weight prep; [256,4352): feat transpose; [4352,6400): zero emax/emin
__global__ void prep_kernel(const float* __restrict__ w0, const float* __restrict__ w1,
                            const float* __restrict__ w2, const float* __restrict__ w3,
                            const float* __restrict__ w4, const float* __restrict__ w5,
                            const float* __restrict__ feat,
                            float* __restrict__ wt, float* __restrict__ featT,
                            float* __restrict__ sum, float* __restrict__ sq,
                            unsigned* __restrict__ emax, unsigned* __restrict__ emin)
{
    int blk = blockIdx.x, tid = threadIdx.x;
    if (blk == 0) { sum[tid] = 0.f; sq[tid] = 0.f; }
    if (blk < 256) {
        const int lo[6]   = {0, 24, 40, 72, 96, 128};
        const int Os[6]   = {64, 64, 128, 64, 128, 256};
        const int Is[6]   = {67, 64, 64, 67, 64, 128};
        const int Ip[6]   = {96, 64, 64, 96, 64, 128};
        const int woff[6] = {0, 6144, 10240, 18432, 24576, 32768};
        const float* Ws[6] = {w0, w1, w2, w3, w4, w5};
        int li = 5;
#pragma unroll
        for (int i = 1; i < 6; ++i) if (blk < lo[i]) { li = i - 1; break; }
        int e = (blk - lo[li]) * 256 + tid;
        int O = Os[li], I = Is[li], Ipad = Ip[li];
        if (e < Ipad * O) {
            int k = e / O, o = e % O;
            int src;
            if (li == 0 || li == 3) {
                // L0 permutation: feat channels first (src 3..66), rel xyz rows 64..66 (src 0..2)
                src = (k < 64) ? (k + 3) : ((k < 67) ? (k - 64) : -1);
            } else {
                src = (k < I) ? k : -1;
            }
            wt[woff[li] + e] = (src >= 0) ? to_tf32(Ws[li][(size_t)o * I + src]) : 0.f;
        }
    } else if (blk < 4352) {
        __shared__ float tile[32][33];
        int t = blk - 256;
        int b = t >> 9;
        int rem = t & 511;
        int c0 = (rem >> 8) * 32;
        int p0 = (rem & 255) * 32;
        int tx = tid & 31, ty = tid >> 5;
#pragma unroll
        for (int i = ty; i < 32; i += 8)
            tile[i][tx] = feat[((size_t)b * 64 + c0 + i) * 8192 + p0 + tx];
        __syncthreads();
#pragma unroll
        for (int i = ty; i < 32; i += 8)
            featT[((size_t)b * 8192 + p0 + i) * 64 + c0 + tx] = tile[tx][i];
    } else {
        // zero emax + emin (2M uints each)
        size_t t = ((size_t)(blk - 4352) * 256 + tid) * 8;
        uint4 z = make_uint4(0, 0, 0, 0);
        if (t < 2097152) {
            *(uint4*)(emax + t) = z; *(uint4*)(emax + t + 4) = z;
        } else {
            size_t u = t - 2097152;
            *(uint4*)(emin + u) = z; *(uint4*)(emin + u + 4) = z;
        }
    }
}

// ---------------- mean over N of xyz ----------------------------------------
__global__ void mean_kernel(const float* __restrict__ xyz, float* __restrict__ meanb)
{
    int b = blockIdx.x, tid = threadIdx.x;
    float sx = 0.f, sy = 0.f, sz = 0.f;
    for (int i = tid; i < 8192; i += 256) {
        const float* q = xyz + ((size_t)b * 8192 + i) * 3;
        sx += q[0]; sy += q[1]; sz += q[2];
    }
    __shared__ float sh[768];
    sh[tid] = sx; sh[256 + tid] = sy; sh[512 + tid] = sz;
    __syncthreads();
    for (int off = 128; off; off >>= 1) {
        if (tid < off) {
            sh[tid]       += sh[tid + off];
            sh[256 + tid] += sh[256 + tid + off];
            sh[512 + tid] += sh[512 + tid + off];
        }
        __syncthreads();
    }
    if (tid == 0) {
        meanb[b * 3 + 0] = sh[0]   / 8192.f;
        meanb[b * 3 + 1] = sh[256] / 8192.f;
        meanb[b * 3 + 2] = sh[512] / 8192.f;
    }
}

// ---------------- farthest point sampling ------------------------------------
__global__ void __launch_bounds__(1024) fps_kernel(
    const float* __restrict__ xyz, const float* __restrict__ meanb,
    float* __restrict__ nxyz)
{
    const int b = blockIdx.x, tid = threadIdx.x;
    const int lane = tid & 31, wid = tid >> 5;
    float px[9], py[9], pz[9], dist[9];
#pragma unroll
    for (int j = 0; j < 9; ++j) {
        int p = j * 1024 + tid;
        if (p < 8193) {
            if (p == 0) {
                px[j] = meanb[b * 3]; py[j] = meanb[b * 3 + 1]; pz[j] = meanb[b * 3 + 2];
            } else {
                const float* q = xyz + ((size_t)b * 8192 + (p - 1)) * 3;
                px[j] = q[0]; py[j] = q[1]; pz[j] = q[2];
            }
        } else { px[j] = 0.f; py[j] = 0.f; pz[j] = 0.f; }
        dist[j] = 1e10f;
    }
    __shared__ float sc[3];
    __shared__ unsigned long long wred[32];
    int far = 0;
    const bool has9 = (tid == 0);
    for (int t = 0; t < 1024; ++t) {
        if ((far & 1023) == tid) {
            int j = far >> 10;
            sc[0] = px[j]; sc[1] = py[j]; sc[2] = pz[j];
            float* o = nxyz + ((size_t)b * 1024 + t) * 3;
            o[0] = px[j]; o[1] = py[j]; o[2] = pz[j];
        }
        __syncthreads();
        float cx = sc[0], cy = sc[1], cz = sc[2];
        float bestv = -1.f;
        int bestj = 0;
#pragma unroll
        for (int j = 0; j < 8; ++j) {
            float dx = px[j] - cx, dy = py[j] - cy, dz = pz[j] - cz;
            float d = __fadd_rn(__fadd_rn(__fmul_rn(dx, dx), __fmul_rn(dy, dy)),
                                __fmul_rn(dz, dz));
            float nd = fminf(dist[j], d);
            dist[j] = nd;
            if (nd > bestv) { bestv = nd; bestj = j; }
        }
        if (has9) {
            float dx = px[8] - cx, dy = py[8] - cy, dz = pz[8] - cz;
            float d = __fadd_rn(__fadd_rn(__fmul_rn(dx, dx), __fmul_rn(dy, dy)),
                                __fmul_rn(dz, dz));
            float nd = fminf(dist[8], d);
            dist[8] = nd;
            if (nd > bestv) { bestv = nd; bestj = 8; }
        }
        unsigned bp = (unsigned)(bestj * 1024 + tid);
        unsigned long long best =
            ((unsigned long long)__float_as_uint(bestv) << 32) |
            (unsigned long long)(0xFFFFFFFFu - bp);
#pragma unroll
        for (int off = 16; off; off >>= 1) {
            unsigned long long o2 = __shfl_down_sync(0xFFFFFFFFu, best, off);
            if (o2 > best) best = o2;
        }
        if (lane == 0) wred[wid] = best;
        __syncthreads();
        unsigned long long v = wred[lane];
#pragma unroll
        for (int off = 16; off; off >>= 1) {
            unsigned long long o2 = __shfl_xor_sync(0xFFFFFFFFu, v, off);
            if (o2 > v) v = o2;
        }
        far = (int)(0xFFFFFFFFu - (unsigned)(v & 0xFFFFFFFFull));
    }
}

// ---------------- ball query: 1 centroid per warp, smem-staged xyz ------------
__global__ void __launch_bounds__(1024) ball_kernel(
    const float* __restrict__ xyz, const float* __restrict__ nxyz,
    int* __restrict__ idx, float r2, int K)
{
    extern __shared__ float sh[];
    float* sx = sh; float* sy = sh + 8192; float* sz = sh + 16384;
    int tid = threadIdx.x;
    int b = blockIdx.x >> 5;
    int sblk = (blockIdx.x & 31) * 32;
    for (int i = tid; i < 8192; i += 1024) {
        const float* q = xyz + ((size_t)b * 8192 + i) * 3;
        sx[i] = q[0]; sy[i] = q[1]; sz[i] = q[2];
    }
    __syncthreads();
    int wid = tid >> 5, lane = tid & 31;
    int w = b * 1024 + sblk + wid;
    float cx = nxyz[(size_t)w * 3], cy = nxyz[(size_t)w * 3 + 1], cz = nxyz[(size_t)w * 3 + 2];
    int cnt = 0, first = 0;
    int* out = idx + (size_t)w * K;
    for (int base = 0; base < 8192; base += 32) {
        int p = base + lane;
        float dx = sx[p] - cx, dy = sy[p] - cy, dz = sz[p] - cz;
        float d2 = __fadd_rn(__fadd_rn(__fmul_rn(dx, dx), __fmul_rn(dy, dy)),
                             __fmul_rn(dz, dz));
        bool in = d2 < r2;
        unsigned mask = __ballot_sync(0xFFFFFFFFu, in);
        if (cnt == 0 && mask) first = base + __ffs(mask) - 1;
        if (in) {
            int pos = cnt + __popc(mask & ((1u << lane) - 1u));
            if (pos < K) out[pos] = p;
        }
        cnt += __popc(mask);
        if (cnt >= K) break;
    }
    if (cnt < K) {
        for (int pos = cnt + lane; pos < K; pos += 32) out[pos] = first;
    }
}

// ---------------- pipelined tensor-core GEMM (templated: fused gather) --------
#define WP 72
#define XP 264
template <bool FUSED>
__global__ void __launch_bounds__(256, 2) gemm_tc2_kernel(
    int O, int I, int Ipad, int M, int K, int logK,
    const float* __restrict__ Wg, const float* __restrict__ X,
    float* __restrict__ Y,
    const float* __restrict__ aa, const float* __restrict__ ad,
    float* __restrict__ gsum, float* __restrict__ gsq,
    unsigned* __restrict__ emax, unsigned* __restrict__ emin,
    const int* __restrict__ idxp, const float* __restrict__ xyzp,
    const float* __restrict__ nxyzp, const float* __restrict__ featT)
{
    extern __shared__ float sm[];
    float* Wt = sm;
    float* Xt = sm + 2 * 32 * WP;
    float* ssum = sm + 2 * 32 * WP + 2 * 32 * XP;
    float* ssq  = ssum + 64;

    const int tid = threadIdx.x, lane = tid & 31, wid = tid >> 5;
    const int warpO = wid >> 2, warpM = wid & 3;
    const int ob = blockIdx.x * 64, mb = blockIdx.y * 256;
    const int r0 = lane >> 2, kq = lane & 3;
    const int kx = tid >> 6;
    const int c4 = (tid & 63) * 4;
    const int NT = Ipad >> 5;

    if (tid < 64) { ssum[tid] = 0.f; ssq[tid] = 0.f; }

    // fused-gather per-thread state (one sample column per thread)
    int pp = 0, bsv = 0, bb = 0;
    const float* fT = featT;
    if (FUSED) {
        int m = mb + tid;
        bsv = m >> logK;
        bb = bsv >> 10;
        pp = idxp[m];
        fT = featT + ((size_t)bb * 8192 + pp) * 64;
    }

    float acc[2][8][4];
#pragma unroll
    for (int r = 0; r < 2; ++r)
#pragma unroll
        for (int nt = 0; nt < 8; ++nt)
#pragma unroll
            for (int c = 0; c < 4; ++c) acc[r][nt][c] = 0.f;

    float4 xr[8];

    auto ldgX = [&](int t) {
        if (FUSED) {
            if (t < 2) {
#pragma unroll
                for (int l = 0; l < 8; ++l)
                    xr[l] = *(const float4*)(fT + t * 32 + l * 4);
            } else {
                const float* q = xyzp + ((size_t)bb * 8192 + pp) * 3;
                const float* c = nxyzp + (size_t)bsv * 3;
                xr[0] = make_float4(q[0], q[1], q[2], 0.f);
                xr[1] = make_float4(c[0], c[1], c[2], 0.f);
            }
        } else {
#pragma unroll
            for (int l = 0; l < 8; ++l) {
                int gk = t * 32 + l * 4 + kx;
                if (gk < I) xr[l] = *(const float4*)(X + (size_t)gk * M + mb + c4);
                else        xr[l] = make_float4(0.f, 0.f, 0.f, 0.f);
            }
        }
    };
    auto stsX = [&](int t, int st) {
        float* Xs = Xt + st * (32 * XP);
        if (FUSED) {
            if (t < 2) {
#pragma unroll
                for (int l = 0; l < 8; ++l) {
                    Xs[(l * 4 + 0) * XP + tid] = to_tf32(xr[l].x);
                    Xs[(l * 4 + 1) * XP + tid] = to_tf32(xr[l].y);
                    Xs[(l * 4 + 2) * XP + tid] = to_tf32(xr[l].z);
                    Xs[(l * 4 + 3) * XP + tid] = to_tf32(xr[l].w);
                }
            } else {
                Xs[0 * XP + tid] = to_tf32(xr[0].x - xr[1].x);
                Xs[1 * XP + tid] = to_tf32(xr[0].y - xr[1].y);
                Xs[2 * XP + tid] = to_tf32(xr[0].z - xr[1].z);
#pragma unroll
                for (int k = 3; k < 32; ++k) Xs[k * XP + tid] = 0.f;
            }
        } else {
#pragma unroll
            for (int l = 0; l < 8; ++l) {
                int k = l * 4 + kx;
                float4 v = xr[l];
                if (aa) {
                    int gk = t * 32 + k;
                    float A_ = aa[gk], D_ = ad[gk];
                    v.x = fmaxf(v.x * A_ + D_, 0.f);
                    v.y = fmaxf(v.y * A_ + D_, 0.f);
                    v.z = fmaxf(v.z * A_ + D_, 0.f);
                    v.w = fmaxf(v.w * A_ + D_, 0.f);
                }
                Xs[k * XP + c4 + 0] = to_tf32(v.x);
                Xs[k * XP + c4 + 1] = to_tf32(v.y);
                Xs[k * XP + c4 + 2] = to_tf32(v.z);
                Xs[k * XP + c4 + 3] = to_tf32(v.w);
            }
        }
    };
    auto cpW = [&](int t, int st) {
        float* Ws = Wt + st * (32 * WP);
#pragma unroll
        for (int l = 0; l < 2; ++l) {
            int e = l * 256 + tid;
            int k = e >> 4, o4 = (e & 15) * 4;
            cp16(&Ws[k * WP + o4], Wg + (size_t)(t * 32 + k) * O + ob + o4);
        }
    };

    ldgX(0);
    cpW(0, 0);
    asm volatile("cp.async.commit_group;\n");
    asm volatile("cp.async.wait_group 0;\n");
    stsX(0, 0);
    if (NT > 1) ldgX(1);
    __syncthreads();

    for (int t = 0; t < NT; ++t) {
        int cur = t & 1, nxt = cur ^ 1;
        if (t + 1 < NT) {
            stsX(t + 1, nxt);
            cpW(t + 1, nxt);
            asm volatile("cp.async.commit_group;\n");
        }
        if (t + 2 < NT) ldgX(t + 2);

        const float* Wc = Wt + cur * (32 * WP);
        const float* Xc = Xt + cur * (32 * XP);
#pragma unroll
        for (int k8 = 0; k8 < 4; ++k8) {
            int kb = k8 * 8;
            uint32_t afr[2][4], bfr[8][2];
#pragma unroll
            for (int r = 0; r < 2; ++r) {
                int o = warpO * 32 + r * 16 + r0;
                afr[r][0] = __float_as_uint(Wc[(kb + kq) * WP + o]);
                afr[r][1] = __float_as_uint(Wc[(kb + kq) * WP + o + 8]);
                afr[r][2] = __float_as_uint(Wc[(kb + kq + 4) * WP + o]);
                afr[r][3] = __float_as_uint(Wc[(kb + kq + 4) * WP + o + 8]);
            }
#pragma unroll
            for (int nt = 0; nt < 8; ++nt) {
                int m = warpM * 64 + nt * 8 + r0;
                bfr[nt][0] = __float_as_uint(Xc[(kb + kq) * XP + m]);
                bfr[nt][1] = __float_as_uint(Xc[(kb + kq + 4) * XP + m]);
            }
#pragma unroll
            for (int r = 0; r < 2; ++r)
#pragma unroll
                for (int nt = 0; nt < 8; ++nt)
                    mma_tf32(acc[r][nt], afr[r], bfr[nt]);
        }
        if (t + 1 < NT) asm volatile("cp.async.wait_group 0;\n");
        __syncthreads();
    }

    // --- epilogue ---
#pragma unroll
    for (int r = 0; r < 2; ++r) {
#pragma unroll
        for (int half = 0; half < 2; ++half) {
            int ol = warpO * 32 + r * 16 + r0 + half * 8;
            float s = 0.f, q = 0.f;
            if (Y) {
                size_t rowoff = (size_t)(ob + ol) * M + mb + warpM * 64 + kq * 2;
#pragma unroll
                for (int nt = 0; nt < 8; ++nt) {
                    float v0 = acc[r][nt][half * 2 + 0];
                    float v1 = acc[r][nt][half * 2 + 1];
                    *(float2*)(Y + rowoff + nt * 8) = make_float2(v0, v1);
                    s += v0 + v1;
                    q += v0 * v0 + v1 * v1;
                }
            } else {
                int ntg = K >> 3;
                for (int g0 = 0; g0 < 8; g0 += ntg) {
                    float mxv = -3.4e38f, mnv = 3.4e38f;
                    for (int nt = g0; nt < g0 + ntg; ++nt) {
                        float v0 = acc[r][nt][half * 2 + 0];
                        float v1 = acc[r][nt][half * 2 + 1];
                        s += v0 + v1;
                        q += v0 * v0 + v1 * v1;
                        mxv = fmaxf(mxv, fmaxf(v0, v1));
                        mnv = fminf(mnv, fminf(v0, v1));
                    }
                    mxv = fmaxf(mxv, __shfl_xor_sync(0xFFFFFFFFu, mxv, 1));
                    mnv = fminf(mnv, __shfl_xor_sync(0xFFFFFFFFu, mnv, 1));
                    mxv = fmaxf(mxv, __shfl_xor_sync(0xFFFFFFFFu, mxv, 2));
                    mnv = fminf(mnv, __shfl_xor_sync(0xFFFFFFFFu, mnv, 2));
                    if (kq == 0) {
                        int bs = (mb + warpM * 64 + g0 * 8) / K;
                        atomicMax(&emax[(size_t)(ob + ol) * 8192 + bs], encf(mxv));
                        atomicMax(&emin[(size_t)(ob + ol) * 8192 + bs], encf(-mnv));
                    }
                }
            }
            s += __shfl_xor_sync(0xFFFFFFFFu, s, 1);
            q += __shfl_xor_sync(0xFFFFFFFFu, q, 1);
            s += __shfl_xor_sync(0xFFFFFFFFu, s, 2);
            q += __shfl_xor_sync(0xFFFFFFFFu, q, 2);
            if (kq == 0) {
                atomicAdd(&ssum[ol], s);
                atomicAdd(&ssq[ol], q);
            }
        }
    }
    __syncthreads();
    if (tid < 64) {
        atomicAdd(&gsum[ob + tid], ssum[tid]);
        atomicAdd(&gsq[ob + tid], ssq[tid]);
    }
}

// ---------------- BN finalize -------------------------------------------------
__global__ void finalize_kernel(float* __restrict__ sum, float* __restrict__ sq,
                                const float* __restrict__ g, const float* __restrict__ bb,
                                float* __restrict__ aa, float* __restrict__ ad,
                                int O, float invn)
{
    int c = threadIdx.x;
    if (c < O) {
        float m = sum[c] * invn;
        float v = sq[c] * invn - m * m;
        float a = g[c] / sqrtf(v + 1e-5f);
        aa[c] = a;
        ad[c] = bb[c] - m * a;
    }
    if (c < 256) { sum[c] = 0.f; sq[c] = 0.f; }
}

// ---------------- final: decode max/min, apply last affine+relu, rezero ------
__global__ void maxfin_kernel(unsigned* __restrict__ emax,
                              unsigned* __restrict__ emin,
                              const float* __restrict__ aa, const float* __restrict__ ad,
                              float* __restrict__ out, int O, int coff)
{
    int gid = blockIdx.x * blockDim.x + threadIdx.x;
    int total = 8 * O * 1024;
    if (gid >= total) return;
    int s = gid & 1023;
    int c = (gid >> 10) % O;
    int b = gid / (O * 1024);
    int bs = b * 1024 + s;
    float a = aa[c], d = ad[c];
    size_t off = (size_t)c * 8192 + bs;
    float y = (a >= 0.f) ? decf(emax[off]) : -decf(emin[off]);
    emax[off] = 0u;   // re-zero for next branch / next replay (prep also zeroes)
    emin[off] = 0u;
    out[((size_t)b * 384 + coff + c) * 1024 + s] = fmaxf(y * a + d, 0.f);
}

// ---------------- host launch ------------------------------------------------
extern "C" void kernel_launch(void* const* d_in, const int* in_sizes, int n_in,
                              void* d_out, int out_size)
{
    (void)in_sizes; (void)n_in; (void)out_size;
    const float* xyz  = (const float*)d_in[0];
    const float* feat = (const float*)d_in[1];
    const float* W[2][3]; const float* G[2][3]; const float* Bb[2][3];
    for (int bi = 0; bi < 2; ++bi)
        for (int li = 0; li < 3; ++li) {
            W[bi][li]  = (const float*)d_in[2 + bi * 9 + li * 3 + 0];
            G[bi][li]  = (const float*)d_in[2 + bi * 9 + li * 3 + 1];
            Bb[bi][li] = (const float*)d_in[2 + bi * 9 + li * 3 + 2];
        }
    float* out      = (float*)d_out;
    float* nxyz     = out;            // (8,1024,3)
    float* feat_out = out + 24576;    // (8,384,1024)

    float *bufA, *bufB, *featT, *meanb, *sum, *sq, *aa, *ad, *wt; int* idxb;
    unsigned *emax, *emin;
    cudaGetSymbolAddress((void**)&bufA, g_bufA);
    cudaGetSymbolAddress((void**)&bufB, g_bufB);
    cudaGetSymbolAddress((void**)&featT, g_featT);
    cudaGetSymbolAddress((void**)&meanb, g_meanb);
    cudaGetSymbolAddress((void**)&idxb, g_idxb);
    cudaGetSymbolAddress((void**)&sum, g_sum);
    cudaGetSymbolAddress((void**)&sq, g_sq);
    cudaGetSymbolAddress((void**)&aa, g_affa);
    cudaGetSymbolAddress((void**)&ad, g_affd);
    cudaGetSymbolAddress((void**)&wt, g_wt);
    cudaGetSymbolAddress((void**)&emax, g_emax);
    cudaGetSymbolAddress((void**)&emin, g_emin);

    const int SMEM_GEMM = (2 * 32 * WP + 2 * 32 * XP + 128) * 4;  // 86528 B
    cudaFuncSetAttribute(gemm_tc2_kernel<true>,
                         cudaFuncAttributeMaxDynamicSharedMemorySize, SMEM_GEMM);
    cudaFuncSetAttribute(gemm_tc2_kernel<false>,
                         cudaFuncAttributeMaxDynamicSharedMemorySize, SMEM_GEMM);
    const int SMEM_BALL = 3 * 8192 * 4;                           // 98304 B
    cudaFuncSetAttribute(ball_kernel,
                         cudaFuncAttributeMaxDynamicSharedMemorySize, SMEM_BALL);

    const int OS[2][4] = { {67, 64, 64, 128}, {67, 64, 128, 256} };
    const int KS[2] = {32, 64};
    const int LOGK[2] = {5, 6};
    const float R2[2] = { (float)(0.4 * 0.4), (float)(0.8 * 0.8) };
    const int IP[2][3]   = { {96, 64, 64}, {96, 64, 128} };
    const int WOFF[2][3] = { {0, 6144, 10240}, {18432, 24576, 32768} };

    prep_kernel<<<6400, 256>>>(W[0][0], W[0][1], W[0][2], W[1][0], W[1][1], W[1][2],
                               feat, wt, featT, sum, sq, emax, emin);
    mean_kernel<<<8, 256>>>(xyz, meanb);
    fps_kernel<<<8, 1024>>>(xyz, meanb, nxyz);

    for (int bi = 0; bi < 2; ++bi) {
        int K = KS[bi];
        int M = 8192 * K;
        float invn = 1.0f / (float)M;

        ball_kernel<<<256, 1024, SMEM_BALL>>>(xyz, nxyz, idxb, R2[bi], K);

        // L0 (fused gather): (O1 x 67) * X0 -> bufB
        {
            dim3 grid(OS[bi][1] / 64, M / 256);
            gemm_tc2_kernel<true><<<grid, 256, SMEM_GEMM>>>(
                OS[bi][1], OS[bi][0], IP[bi][0], M, K, LOGK[bi], wt + WOFF[bi][0],
                nullptr, bufB, nullptr, nullptr, sum, sq, nullptr, nullptr,
                idxb, xyz, nxyz, featT);
            finalize_kernel<<<1, 256>>>(sum, sq, G[bi][0], Bb[bi][0], aa, ad, OS[bi][1], invn);
        }
        // L1: (O2 x O1) * act(bufB) -> bufA
        {
            dim3 grid(OS[bi][2] / 64, M / 256);
            gemm_tc2_kernel<false><<<grid, 256, SMEM_GEMM>>>(
                OS[bi][2], OS[bi][1], IP[bi][1], M, K, LOGK[bi], wt + WOFF[bi][1],
                bufB, bufA, aa, ad, sum, sq, nullptr, nullptr,
                nullptr, nullptr, nullptr, nullptr);
            finalize_kernel<<<1, 256>>>(sum, sq, G[bi][1], Bb[bi][1], aa, ad, OS[bi][2], invn);
        }
        // L2: (O3 x O2) * act(bufA) -> fused max/min epilogue (no Y write)
        {
            dim3 grid(OS[bi][3] / 64, M / 256);
            gemm_tc2_kernel<false><<<grid, 256, SMEM_GEMM>>>(
                OS[bi][3], OS[bi][2], IP[bi][2], M, K, LOGK[bi], wt + WOFF[bi][2],
                bufA, nullptr, aa, ad, sum, sq, emax, emin,
                nullptr, nullptr, nullptr, nullptr);
            finalize_kernel<<<1, 256>>>(sum, sq, G[bi][2], Bb[bi][2], aa, ad, OS[bi][3], invn);
        }
        // decode + final affine + relu -> output (also re-zeroes emax/emin)
        {
            int total = 8 * OS[bi][3] * 1024;
            maxfin_kernel<<<(total + 255) / 256, 256>>>(emax, emin, aa, ad, feat_out,
                                                        OS[bi][3], bi == 0 ? 0 : 128);
        }
    }
}

// round 13
// speedup vs baseline: 1.2174x; 1.1547x over previous
#include <cuda_runtime.h>
#include <cstdint>
#include <cstddef>

// ---------------- scratch (static device memory; no allocs allowed) ----------
static __device__ float g_bufA[(size_t)192 * 524288];   // 402 MB (L1 outs, both branches)
static __device__ float g_bufB[(size_t)128 * 524288];   // 268 MB (L0 outs, both branches)
static __device__ float g_featT[(size_t)8 * 8192 * 64]; // 16 MB transposed features
static __device__ int   g_idx0[8 * 1024 * 32];
static __device__ int   g_idx1[8 * 1024 * 64];
static __device__ float g_sum0[256], g_sq0[256], g_sum1[256], g_sq1[256];
static __device__ float g_affa0[256], g_affd0[256], g_affa1[256], g_affd1[256];
static __device__ float g_wt[65536];                    // pre-transposed tf32 weights
static __device__ unsigned g_emax0[128 * 8192], g_emin0[128 * 8192];
static __device__ unsigned g_emax1[256 * 8192], g_emin1[256 * 8192];

// ---------------- helpers ----------------------------------------------------
__device__ __forceinline__ float to_tf32(float x)
{
    uint32_t r;
    asm volatile("cvt.rna.tf32.f32 %0, %1;\n" : "=r"(r) : "f"(x));
    return __uint_as_float(r);
}
__device__ __forceinline__ void mma_tf32(float* d, const uint32_t* a, const uint32_t* b)
{
    asm volatile(
        "mma.sync.aligned.m16n8k8.row.col.f32.tf32.tf32.f32 "
        "{%0,%1,%2,%3}, {%4,%5,%6,%7}, {%8,%9}, {%0,%1,%2,%3};\n"
        : "+f"(d[0]), "+f"(d[1]), "+f"(d[2]), "+f"(d[3])
        : "r"(a[0]), "r"(a[1]), "r"(a[2]), "r"(a[3]),
          "r"(b[0]), "r"(b[1]));
}
__device__ __forceinline__ void cp16(void* dst, const void* src)
{
    uint32_t d = (uint32_t)__cvta_generic_to_shared(dst);
    asm volatile("cp.async.ca.shared.global [%0], [%1], 16;\n" :: "r"(d), "l"(src));
}
__device__ __forceinline__ unsigned encf(float f)
{
    unsigned u = __float_as_uint(f);
    return (u >> 31) ? ~u : (u | 0x80000000u);
}
__device__ __forceinline__ float decf(unsigned u)
{
    return __uint_as_float((u >> 31) ? (u & 0x7FFFFFFFu) : ~u);
}
__device__ __forceinline__ unsigned redux_max_u32(unsigned v)
{
    unsigned r;
    asm volatile("redux.sync.max.u32 %0, %1, 0xffffffff;" : "=r"(r) : "r"(v));
    return r;
}
__device__ __forceinline__ unsigned redux_min_u32(unsigned v)
{
    unsigned r;
    asm volatile("redux.sync.min.u32 %0, %1, 0xffffffff;" : "=r"(r) : "r"(v));
    return r;
}

// ---------------- prep: weights + feat transpose + zero stats/extrema --------
// blocks [0,256): weights; [256,4352): feat transpose; [4352,7424): zero emax/emin
__global__ void prep_kernel(const float* __restrict__ w0, const float* __restrict__ w1,
                            const float* __restrict__ w2, const float* __restrict__ w3,
                            const float* __restrict__ w4, const float* __restrict__ w5,
                            const float* __restrict__ feat,
                            float* __restrict__ wt, float* __restrict__ featT,
                            float* __restrict__ sum0, float* __restrict__ sq0,
                            float* __restrict__ sum1, float* __restrict__ sq1,
                            unsigned* __restrict__ emax0, unsigned* __restrict__ emin0,
                            unsigned* __restrict__ emax1, unsigned* __restrict__ emin1)
{
    int blk = blockIdx.x, tid = threadIdx.x;
    if (blk == 0) { sum0[tid] = 0.f; sq0[tid] = 0.f; }
    if (blk == 1) { sum1[tid] = 0.f; sq1[tid] = 0.f; }
    if (blk < 256) {
        const int lo[6]   = {0, 24, 40, 72, 96, 128};
        const int Os[6]   = {64, 64, 128, 64, 128, 256};
        const int Is[6]   = {67, 64, 64, 67, 64, 128};
        const int Ip[6]   = {96, 64, 64, 96, 64, 128};
        const int woff[6] = {0, 6144, 10240, 18432, 24576, 32768};
        const float* Ws[6] = {w0, w1, w2, w3, w4, w5};
        int li = 5;
#pragma unroll
        for (int i = 1; i < 6; ++i) if (blk < lo[i]) { li = i - 1; break; }
        int e = (blk - lo[li]) * 256 + tid;
        int O = Os[li], I = Is[li], Ipad = Ip[li];
        if (e < Ipad * O) {
            int k = e / O, o = e % O;
            int src;
            if (li == 0 || li == 3) {
                src = (k < 64) ? (k + 3) : ((k < 67) ? (k - 64) : -1);
            } else {
                src = (k < I) ? k : -1;
            }
            wt[woff[li] + e] = (src >= 0) ? to_tf32(Ws[li][(size_t)o * I + src]) : 0.f;
        }
    } else if (blk < 4352) {
        __shared__ float tile[32][33];
        int t = blk - 256;
        int b = t >> 9;
        int rem = t & 511;
        int c0 = (rem >> 8) * 32;
        int p0 = (rem & 255) * 32;
        int tx = tid & 31, ty = tid >> 5;
#pragma unroll
        for (int i = ty; i < 32; i += 8)
            tile[i][tx] = feat[((size_t)b * 64 + c0 + i) * 8192 + p0 + tx];
        __syncthreads();
#pragma unroll
        for (int i = ty; i < 32; i += 8)
            featT[((size_t)b * 8192 + p0 + i) * 64 + c0 + tx] = tile[tx][i];
    } else {
        // zero 6291456 u32 total: emax0/emin0 (1M each), emax1/emin1 (2M each)
        size_t t = ((size_t)(blk - 4352) * 256 + tid) * 8;
        uint4 z = make_uint4(0, 0, 0, 0);
        unsigned* dst;
        size_t o;
        if (t < 1048576)      { dst = emax0; o = t; }
        else if (t < 2097152) { dst = emin0; o = t - 1048576; }
        else if (t < 4194304) { dst = emax1; o = t - 2097152; }
        else                  { dst = emin1; o = t - 4194304; }
        *(uint4*)(dst + o) = z;
        *(uint4*)(dst + o + 4) = z;
    }
}

// ---------------- farthest point sampling (mean fused, redux reductions) ------
__global__ void __launch_bounds__(1024) fps_kernel(
    const float* __restrict__ xyz, float* __restrict__ nxyz)
{
    const int b = blockIdx.x, tid = threadIdx.x;
    const int lane = tid & 31, wid = tid >> 5;
    float px[9], py[9], pz[9], dist[9];
    float msx = 0.f, msy = 0.f, msz = 0.f;
#pragma unroll
    for (int j = 0; j < 9; ++j) {
        int p = j * 1024 + tid;
        px[j] = 0.f; py[j] = 0.f; pz[j] = 0.f;
        if (p >= 1 && p < 8193) {
            const float* q = xyz + ((size_t)b * 8192 + (p - 1)) * 3;
            px[j] = q[0]; py[j] = q[1]; pz[j] = q[2];
            msx += q[0]; msy += q[1]; msz += q[2];
        }
        dist[j] = 1e10f;
    }
    __shared__ float red[96];
    __shared__ float sc[3];
    __shared__ unsigned svals[32], sbps[32];
    // block-reduce mean (once)
#pragma unroll
    for (int off = 16; off; off >>= 1) {
        msx += __shfl_xor_sync(0xFFFFFFFFu, msx, off);
        msy += __shfl_xor_sync(0xFFFFFFFFu, msy, off);
        msz += __shfl_xor_sync(0xFFFFFFFFu, msz, off);
    }
    if (lane == 0) { red[wid] = msx; red[32 + wid] = msy; red[64 + wid] = msz; }
    __syncthreads();
    if (tid == 0) {
        float ax = 0.f, ay = 0.f, az = 0.f;
        for (int i = 0; i < 32; ++i) { ax += red[i]; ay += red[32 + i]; az += red[64 + i]; }
        px[0] = ax / 8192.f; py[0] = ay / 8192.f; pz[0] = az / 8192.f;
    }
    int far = 0;
    const bool has9 = (tid == 0);
    for (int t = 0; t < 1024; ++t) {
        if ((far & 1023) == tid) {
            int j = far >> 10;
            sc[0] = px[j]; sc[1] = py[j]; sc[2] = pz[j];
            float* o = nxyz + ((size_t)b * 1024 + t) * 3;
            o[0] = px[j]; o[1] = py[j]; o[2] = pz[j];
        }
        __syncthreads();
        float cx = sc[0], cy = sc[1], cz = sc[2];
        float bestv = -1.f;
        int bestj = 0;
#pragma unroll
        for (int j = 0; j < 8; ++j) {
            float dx = px[j] - cx, dy = py[j] - cy, dz = pz[j] - cz;
            float d = __fadd_rn(__fadd_rn(__fmul_rn(dx, dx), __fmul_rn(dy, dy)),
                                __fmul_rn(dz, dz));
            float nd = fminf(dist[j], d);
            dist[j] = nd;
            if (nd > bestv) { bestv = nd; bestj = j; }   // strict >: first index wins
        }
        if (has9) {
            float dx = px[8] - cx, dy = py[8] - cy, dz = pz[8] - cz;
            float d = __fadd_rn(__fadd_rn(__fmul_rn(dx, dx), __fmul_rn(dy, dy)),
                                __fmul_rn(dz, dz));
            float nd = fminf(dist[8], d);
            dist[8] = nd;
            if (nd > bestv) { bestv = nd; bestj = 8; }
        }
        // bestv >= 0 -> float bits monotone; warp argmax via redux
        unsigned bb_ = __float_as_uint(bestv);
        unsigned bp  = (unsigned)(bestj * 1024 + tid);
        unsigned wmax = redux_max_u32(bb_);
        unsigned cand = (bb_ == wmax) ? bp : 0xFFFFFFFFu;
        unsigned wbp  = redux_min_u32(cand);
        if (lane == 0) { svals[wid] = wmax; sbps[wid] = wbp; }
        __syncthreads();
        unsigned v = svals[lane], pb = sbps[lane];
        unsigned gmax = redux_max_u32(v);
        unsigned c2 = (v == gmax) ? pb : 0xFFFFFFFFu;
        far = (int)redux_min_u32(c2);
    }
}

// ---------------- ball query, both branches in one launch ---------------------
__global__ void __launch_bounds__(1024) ball_kernel(
    const float* __restrict__ xyz, const float* __restrict__ nxyz,
    int* __restrict__ idx0, int* __restrict__ idx1, float r2a, float r2b)
{
    extern __shared__ float sh[];
    float* sx = sh; float* sy = sh + 8192; float* sz = sh + 16384;
    int tid = threadIdx.x;
    int blk = blockIdx.x;
    int K; int* idx; float r2; int local;
    if (blk < 256) { K = 32; idx = idx0; r2 = r2a; local = blk; }
    else           { K = 64; idx = idx1; r2 = r2b; local = blk - 256; }
    int b = local >> 5;
    int sblk = (local & 31) * 32;
    for (int i = tid; i < 8192; i += 1024) {
        const float* q = xyz + ((size_t)b * 8192 + i) * 3;
        sx[i] = q[0]; sy[i] = q[1]; sz[i] = q[2];
    }
    __syncthreads();
    int wid = tid >> 5, lane = tid & 31;
    int w = b * 1024 + sblk + wid;
    float cx = nxyz[(size_t)w * 3], cy = nxyz[(size_t)w * 3 + 1], cz = nxyz[(size_t)w * 3 + 2];
    int cnt = 0, first = 0;
    int* out = idx + (size_t)w * K;
    for (int base = 0; base < 8192; base += 32) {
        int p = base + lane;
        float dx = sx[p] - cx, dy = sy[p] - cy, dz = sz[p] - cz;
        float d2 = __fadd_rn(__fadd_rn(__fmul_rn(dx, dx), __fmul_rn(dy, dy)),
                             __fmul_rn(dz, dz));
        bool in = d2 < r2;
        unsigned mask = __ballot_sync(0xFFFFFFFFu, in);
        if (cnt == 0 && mask) first = base + __ffs(mask) - 1;
        if (in) {
            int pos = cnt + __popc(mask & ((1u << lane) - 1u));
            if (pos < K) out[pos] = p;
        }
        cnt += __popc(mask);
        if (cnt >= K) break;
    }
    if (cnt < K) {
        for (int pos = cnt + lane; pos < K; pos += 32) out[pos] = first;
    }
}

// ---------------- pipelined tensor-core GEMM, both branches per launch --------
struct GP {
    int O, Ipad, M, K, logK, nblk, obtiles;
    const float* Wg;
    const float* X;
    float* Y;
    const float* aa;
    const float* ad;
    float* gsum;
    float* gsq;
    unsigned* emax;
    unsigned* emin;
    const int* idxp;
};

#define WP 72
#define XP 264
template <bool FUSED>
__global__ void __launch_bounds__(256, 2) gemm_tc2_kernel(
    GP gpa, GP gpb,
    const float* __restrict__ xyzp, const float* __restrict__ nxyzp,
    const float* __restrict__ featT)
{
    extern __shared__ float sm[];
    float* Wt = sm;
    float* Xt = sm + 2 * 32 * WP;
    float* ssum = sm + 2 * 32 * WP + 2 * 32 * XP;
    float* ssq  = ssum + 64;

    GP P;
    int bid = blockIdx.x;
    if (bid < gpa.nblk) { P = gpa; } else { P = gpb; bid -= gpa.nblk; }

    const int tid = threadIdx.x, lane = tid & 31, wid = tid >> 5;
    const int warpO = wid >> 2, warpM = wid & 3;
    const int ob = (bid % P.obtiles) * 64;
    const int mb = (bid / P.obtiles) * 256;
    const int r0 = lane >> 2, kq = lane & 3;
    const int kx = tid >> 6;
    const int c4 = (tid & 63) * 4;
    const int NT = P.Ipad >> 5;

    if (tid < 64) { ssum[tid] = 0.f; ssq[tid] = 0.f; }

    // fused-gather per-thread state (one sample column per thread)
    int pp = 0, bsv = 0, bb = 0;
    const float* fT = featT;
    if (FUSED) {
        int m = mb + tid;
        bsv = m >> P.logK;
        bb = bsv >> 10;
        pp = P.idxp[m];
        fT = featT + ((size_t)bb * 8192 + pp) * 64;
    }

    float acc[2][8][4];
#pragma unroll
    for (int r = 0; r < 2; ++r)
#pragma unroll
        for (int nt = 0; nt < 8; ++nt)
#pragma unroll
            for (int c = 0; c < 4; ++c) acc[r][nt][c] = 0.f;

    float4 xr[8];

    auto ldgX = [&](int t) {
        if (FUSED) {
            if (t < 2) {
#pragma unroll
                for (int l = 0; l < 8; ++l)
                    xr[l] = *(const float4*)(fT + t * 32 + l * 4);
            } else {
                const float* q = xyzp + ((size_t)bb * 8192 + pp) * 3;
                const float* c = nxyzp + (size_t)bsv * 3;
                xr[0] = make_float4(q[0], q[1], q[2], 0.f);
                xr[1] = make_float4(c[0], c[1], c[2], 0.f);
            }
        } else {
#pragma unroll
            for (int l = 0; l < 8; ++l) {
                int gk = t * 32 + l * 4 + kx;
                xr[l] = *(const float4*)(P.X + (size_t)gk * P.M + mb + c4);
            }
        }
    };
    auto stsX = [&](int t, int st) {
        float* Xs = Xt + st * (32 * XP);
        if (FUSED) {
            if (t < 2) {
#pragma unroll
                for (int l = 0; l < 8; ++l) {
                    Xs[(l * 4 + 0) * XP + tid] = to_tf32(xr[l].x);
                    Xs[(l * 4 + 1) * XP + tid] = to_tf32(xr[l].y);
                    Xs[(l * 4 + 2) * XP + tid] = to_tf32(xr[l].z);
                    Xs[(l * 4 + 3) * XP + tid] = to_tf32(xr[l].w);
                }
            } else {
                Xs[0 * XP + tid] = to_tf32(xr[0].x - xr[1].x);
                Xs[1 * XP + tid] = to_tf32(xr[0].y - xr[1].y);
                Xs[2 * XP + tid] = to_tf32(xr[0].z - xr[1].z);
#pragma unroll
                for (int k = 3; k < 32; ++k) Xs[k * XP + tid] = 0.f;
            }
        } else {
#pragma unroll
            for (int l = 0; l < 8; ++l) {
                int k = l * 4 + kx;
                float4 v = xr[l];
                if (P.aa) {
                    int gk = t * 32 + k;
                    float A_ = P.aa[gk], D_ = P.ad[gk];
                    v.x = fmaxf(v.x * A_ + D_, 0.f);
                    v.y = fmaxf(v.y * A_ + D_, 0.f);
                    v.z = fmaxf(v.z * A_ + D_, 0.f);
                    v.w = fmaxf(v.w * A_ + D_, 0.f);
                }
                Xs[k * XP + c4 + 0] = to_tf32(v.x);
                Xs[k * XP + c4 + 1] = to_tf32(v.y);
                Xs[k * XP + c4 + 2] = to_tf32(v.z);
                Xs[k * XP + c4 + 3] = to_tf32(v.w);
            }
        }
    };
    auto cpW = [&](int t, int st) {
        float* Ws = Wt + st * (32 * WP);
#pragma unroll
        for (int l = 0; l < 2; ++l) {
            int e = l * 256 + tid;
            int k = e >> 4, o4 = (e & 15) * 4;
            cp16(&Ws[k * WP + o4], P.Wg + (size_t)(t * 32 + k) * P.O + ob + o4);
        }
    };

    ldgX(0);
    cpW(0, 0);
    asm volatile("cp.async.commit_group;\n");
    asm volatile("cp.async.wait_group 0;\n");
    stsX(0, 0);
    if (NT > 1) ldgX(1);
    __syncthreads();

    for (int t = 0; t < NT; ++t) {
        int cur = t & 1, nxt = cur ^ 1;
        if (t + 1 < NT) {
            stsX(t + 1, nxt);
            cpW(t + 1, nxt);
            asm volatile("cp.async.commit_group;\n");
        }
        if (t + 2 < NT) ldgX(t + 2);

        const float* Wc = Wt + cur * (32 * WP);
        const float* Xc = Xt + cur * (32 * XP);
#pragma unroll
        for (int k8 = 0; k8 < 4; ++k8) {
            int kb = k8 * 8;
            uint32_t afr[2][4], bfr[8][2];
#pragma unroll
            for (int r = 0; r < 2; ++r) {
                int o = warpO * 32 + r * 16 + r0;
                afr[r][0] = __float_as_uint(Wc[(kb + kq) * WP + o]);
                afr[r][1] = __float_as_uint(Wc[(kb + kq) * WP + o + 8]);
                afr[r][2] = __float_as_uint(Wc[(kb + kq + 4) * WP + o]);
                afr[r][3] = __float_as_uint(Wc[(kb + kq + 4) * WP + o + 8]);
            }
#pragma unroll
            for (int nt = 0; nt < 8; ++nt) {
                int m = warpM * 64 + nt * 8 + r0;
                bfr[nt][0] = __float_as_uint(Xc[(kb + kq) * XP + m]);
                bfr[nt][1] = __float_as_uint(Xc[(kb + kq + 4) * XP + m]);
            }
#pragma unroll
            for (int r = 0; r < 2; ++r)
#pragma unroll
                for (int nt = 0; nt < 8; ++nt)
                    mma_tf32(acc[r][nt], afr[r], bfr[nt]);
        }
        if (t + 1 < NT) asm volatile("cp.async.wait_group 0;\n");
        __syncthreads();
    }

    // --- epilogue ---
#pragma unroll
    for (int r = 0; r < 2; ++r) {
#pragma unroll
        for (int half = 0; half < 2; ++half) {
            int ol = warpO * 32 + r * 16 + r0 + half * 8;
            float s = 0.f, q = 0.f;
            if (P.Y) {
                size_t rowoff = (size_t)(ob + ol) * P.M + mb + warpM * 64 + kq * 2;
#pragma unroll
                for (int nt = 0; nt < 8; ++nt) {
                    float v0 = acc[r][nt][half * 2 + 0];
                    float v1 = acc[r][nt][half * 2 + 1];
                    *(float2*)(P.Y + rowoff + nt * 8) = make_float2(v0, v1);
                    s += v0 + v1;
                    q += v0 * v0 + v1 * v1;
                }
            } else {
                int ntg = P.K >> 3;
                for (int g0 = 0; g0 < 8; g0 += ntg) {
                    float mxv = -3.4e38f, mnv = 3.4e38f;
                    for (int nt = g0; nt < g0 + ntg; ++nt) {
                        float v0 = acc[r][nt][half * 2 + 0];
                        float v1 = acc[r][nt][half * 2 + 1];
                        s += v0 + v1;
                        q += v0 * v0 + v1 * v1;
                        mxv = fmaxf(mxv, fmaxf(v0, v1));
                        mnv = fminf(mnv, fminf(v0, v1));
                    }
                    mxv = fmaxf(mxv, __shfl_xor_sync(0xFFFFFFFFu, mxv, 1));
                    mnv = fminf(mnv, __shfl_xor_sync(0xFFFFFFFFu, mnv, 1));
                    mxv = fmaxf(mxv, __shfl_xor_sync(0xFFFFFFFFu, mxv, 2));
                    mnv = fminf(mnv, __shfl_xor_sync(0xFFFFFFFFu, mnv, 2));
                    if (kq == 0) {
                        int bs = (mb + warpM * 64 + g0 * 8) >> P.logK;
                        atomicMax(&P.emax[(size_t)(ob + ol) * 8192 + bs], encf(mxv));
                        atomicMax(&P.emin[(size_t)(ob + ol) * 8192 + bs], encf(-mnv));
                    }
                }
            }
            s += __shfl_xor_sync(0xFFFFFFFFu, s, 1);
            q += __shfl_xor_sync(0xFFFFFFFFu, q, 1);
            s += __shfl_xor_sync(0xFFFFFFFFu, s, 2);
            q += __shfl_xor_sync(0xFFFFFFFFu, q, 2);
            if (kq == 0) {
                atomicAdd(&ssum[ol], s);
                atomicAdd(&ssq[ol], q);
            }
        }
    }
    __syncthreads();
    if (tid < 64) {
        atomicAdd(&P.gsum[ob + tid], ssum[tid]);
        atomicAdd(&P.gsq[ob + tid], ssq[tid]);
    }
}

// ---------------- BN finalize, both branches (grid 2) -------------------------
__global__ void finalize_kernel(
    float* sum0, float* sq0, const float* g0, const float* bb0,
    float* aa0, float* ad0, int O0, float invn0,
    float* sum1, float* sq1, const float* g1, const float* bb1,
    float* aa1, float* ad1, int O1, float invn1)
{
    float *sum, *sq, *aa, *ad; const float *g, *bb; int O; float invn;
    if (blockIdx.x == 0) { sum = sum0; sq = sq0; g = g0; bb = bb0; aa = aa0; ad = ad0; O = O0; invn = invn0; }
    else                 { sum = sum1; sq = sq1; g = g1; bb = bb1; aa = aa1; ad = ad1; O = O1; invn = invn1; }
    int c = threadIdx.x;
    if (c < O) {
        float m = sum[c] * invn;
        float v = sq[c] * invn - m * m;
        float a = g[c] / sqrtf(v + 1e-5f);
        aa[c] = a;
        ad[c] = bb[c] - m * a;
    }
    if (c < 256) { sum[c] = 0.f; sq[c] = 0.f; }
}

// ---------------- final: decode max/min + last affine+relu, both branches -----
__global__ void maxfin_kernel(
    const unsigned* __restrict__ emax0, const unsigned* __restrict__ emin0,
    const unsigned* __restrict__ emax1, const unsigned* __restrict__ emin1,
    const float* __restrict__ aa0, const float* __restrict__ ad0,
    const float* __restrict__ aa1, const float* __restrict__ ad1,
    float* __restrict__ out)
{
    int gid = blockIdx.x * 256 + threadIdx.x;
    const unsigned *emax, *emin; const float *aa, *ad;
    int O, coff, id;
    if (gid < 1048576) {
        id = gid; O = 128; coff = 0; emax = emax0; emin = emin0; aa = aa0; ad = ad0;
    } else {
        id = gid - 1048576;
        O = 256; coff = 128; emax = emax1; emin = emin1; aa = aa1; ad = ad1;
    }
    int s = id & 1023;
    int c = (id >> 10) % O;
    int b = id / (O * 1024);
    int bs = b * 1024 + s;
    float a = aa[c], d = ad[c];
    size_t off = (size_t)c * 8192 + bs;
    float y = (a >= 0.f) ? decf(emax[off]) : -decf(emin[off]);
    out[((size_t)b * 384 + coff + c) * 1024 + s] = fmaxf(y * a + d, 0.f);
}

// ---------------- host launch ------------------------------------------------
extern "C" void kernel_launch(void* const* d_in, const int* in_sizes, int n_in,
                              void* d_out, int out_size)
{
    (void)in_sizes; (void)n_in; (void)out_size;
    const float* xyz  = (const float*)d_in[0];
    const float* feat = (const float*)d_in[1];
    const float* W[2][3]; const float* G[2][3]; const float* Bb[2][3];
    for (int bi = 0; bi < 2; ++bi)
        for (int li = 0; li < 3; ++li) {
            W[bi][li]  = (const float*)d_in[2 + bi * 9 + li * 3 + 0];
            G[bi][li]  = (const float*)d_in[2 + bi * 9 + li * 3 + 1];
            Bb[bi][li] = (const float*)d_in[2 + bi * 9 + li * 3 + 2];
        }
    float* out      = (float*)d_out;
    float* nxyz     = out;            // (8,1024,3)
    float* feat_out = out + 24576;    // (8,384,1024)

    float *bufA, *bufB, *featT, *wt;
    float *sum0, *sq0, *sum1, *sq1, *aa0, *ad0, *aa1, *ad1;
    int *idx0, *idx1;
    unsigned *emax0, *emin0, *emax1, *emin1;
    cudaGetSymbolAddress((void**)&bufA, g_bufA);
    cudaGetSymbolAddress((void**)&bufB, g_bufB);
    cudaGetSymbolAddress((void**)&featT, g_featT);
    cudaGetSymbolAddress((void**)&wt, g_wt);
    cudaGetSymbolAddress((void**)&sum0, g_sum0);
    cudaGetSymbolAddress((void**)&sq0, g_sq0);
    cudaGetSymbolAddress((void**)&sum1, g_sum1);
    cudaGetSymbolAddress((void**)&sq1, g_sq1);
    cudaGetSymbolAddress((void**)&aa0, g_affa0);
    cudaGetSymbolAddress((void**)&ad0, g_affd0);
    cudaGetSymbolAddress((void**)&aa1, g_affa1);
    cudaGetSymbolAddress((void**)&ad1, g_affd1);
    cudaGetSymbolAddress((void**)&idx0, g_idx0);
    cudaGetSymbolAddress((void**)&idx1, g_idx1);
    cudaGetSymbolAddress((void**)&emax0, g_emax0);
    cudaGetSymbolAddress((void**)&emin0, g_emin0);
    cudaGetSymbolAddress((void**)&emax1, g_emax1);
    cudaGetSymbolAddress((void**)&emin1, g_emin1);

    const int SMEM_GEMM = (2 * 32 * WP + 2 * 32 * XP + 128) * 4;  // 86528 B
    cudaFuncSetAttribute(gemm_tc2_kernel<true>,
                         cudaFuncAttributeMaxDynamicSharedMemorySize, SMEM_GEMM);
    cudaFuncSetAttribute(gemm_tc2_kernel<false>,
                         cudaFuncAttributeMaxDynamicSharedMemorySize, SMEM_GEMM);
    const int SMEM_BALL = 3 * 8192 * 4;                           // 98304 B
    cudaFuncSetAttribute(ball_kernel,
                         cudaFuncAttributeMaxDynamicSharedMemorySize, SMEM_BALL);

    const int M0 = 262144, M1 = 524288;
    const float invn0 = 1.f / (float)M0, invn1 = 1.f / (float)M1;
    float* YB0 = bufB;
    float* YB1 = bufB + (size_t)64 * M0;
    float* YA0 = bufA;
    float* YA1 = bufA + (size_t)64 * M0;

    prep_kernel<<<7424, 256>>>(W[0][0], W[0][1], W[0][2], W[1][0], W[1][1], W[1][2],
                               feat, wt, featT, sum0, sq0, sum1, sq1,
                               emax0, emin0, emax1, emin1);
    fps_kernel<<<8, 1024>>>(xyz, nxyz);
    ball_kernel<<<512, 1024, SMEM_BALL>>>(xyz, nxyz, idx0, idx1,
                                          (float)(0.4 * 0.4), (float)(0.8 * 0.8));

    // ---- L0 (fused gather) ----
    {
        GP a = {64, 96, M0, 32, 5, 1024, 1, wt + 0,     nullptr, YB0,
                nullptr, nullptr, sum0, sq0, nullptr, nullptr, idx0};
        GP b = {64, 96, M1, 64, 6, 2048, 1, wt + 18432, nullptr, YB1,
                nullptr, nullptr, sum1, sq1, nullptr, nullptr, idx1};
        gemm_tc2_kernel<true><<<3072, 256, SMEM_GEMM>>>(a, b, xyz, nxyz, featT);
        finalize_kernel<<<2, 256>>>(sum0, sq0, G[0][0], Bb[0][0], aa0, ad0, 64, invn0,
                                    sum1, sq1, G[1][0], Bb[1][0], aa1, ad1, 64, invn1);
    }
    // ---- L1 ----
    {
        GP a = {64,  64, M0, 32, 5, 1024, 1, wt + 6144,  YB0, YA0,
                aa0, ad0, sum0, sq0, nullptr, nullptr, nullptr};
        GP b = {128, 64, M1, 64, 6, 4096, 2, wt + 24576, YB1, YA1,
                aa1, ad1, sum1, sq1, nullptr, nullptr, nullptr};
        gemm_tc2_kernel<false><<<5120, 256, SMEM_GEMM>>>(a, b, xyz, nxyz, featT);
        finalize_kernel<<<2, 256>>>(sum0, sq0, G[0][1], Bb[0][1], aa0, ad0, 64, invn0,
                                    sum1, sq1, G[1][1], Bb[1][1], aa1, ad1, 128, invn1);
    }
    // ---- L2 (fused max/min epilogue, no Y write) ----
    {
        GP a = {128, 64,  M0, 32, 5, 2048, 2, wt + 10240, YA0, nullptr,
                aa0, ad0, sum0, sq0, emax0, emin0, nullptr};
        GP b = {256, 128, M1, 64, 6, 8192, 4, wt + 32768, YA1, nullptr,
                aa1, ad1, sum1, sq1, emax1, emin1, nullptr};
        gemm_tc2_kernel<false><<<10240, 256, SMEM_GEMM>>>(a, b, xyz, nxyz, featT);
        finalize_kernel<<<2, 256>>>(sum0, sq0, G[0][2], Bb[0][2], aa0, ad0, 128, invn0,
                                    sum1, sq1, G[1][2], Bb[1][2], aa1, ad1, 256, invn1);
    }
    // ---- decode + final affine + relu -> output (both branches) ----
    maxfin_kernel<<<12288, 256>>>(emax0, emin0, emax1, emin1,
                                  aa0, ad0, aa1, ad1, feat_out);
}

// round 15
// speedup vs baseline: 1.2431x; 1.0211x over previous
#include <cuda_runtime.h>
#include <cstdint>
#include <cstddef>

// ---------------- scratch (static device memory; no allocs allowed) ----------
static __device__ float g_bufA[(size_t)192 * 524288];   // 402 MB (L1 outs, both branches)
static __device__ float g_bufB[(size_t)128 * 524288];   // 268 MB (L0 outs, both branches)
static __device__ float g_featT[(size_t)8 * 8192 * 64]; // 16 MB transposed features
static __device__ int   g_idx0[8 * 1024 * 32];
static __device__ int   g_idx1[8 * 1024 * 64];
static __device__ float g_sum0[256], g_sq0[256], g_sum1[256], g_sq1[256];
static __device__ float g_affa0[256], g_affd0[256], g_affa1[256], g_affd1[256];
static __device__ float g_wt[65536];                    // pre-transposed tf32 weights
static __device__ unsigned g_emax0[128 * 8192], g_emin0[128 * 8192];
static __device__ unsigned g_emax1[256 * 8192], g_emin1[256 * 8192];

// ---------------- helpers ----------------------------------------------------
__device__ __forceinline__ float to_tf32(float x)
{
    uint32_t r;
    asm volatile("cvt.rna.tf32.f32 %0, %1;\n" : "=r"(r) : "f"(x));
    return __uint_as_float(r);
}
__device__ __forceinline__ void mma_tf32(float* d, const uint32_t* a, const uint32_t* b)
{
    asm volatile(
        "mma.sync.aligned.m16n8k8.row.col.f32.tf32.tf32.f32 "
        "{%0,%1,%2,%3}, {%4,%5,%6,%7}, {%8,%9}, {%0,%1,%2,%3};\n"
        : "+f"(d[0]), "+f"(d[1]), "+f"(d[2]), "+f"(d[3])
        : "r"(a[0]), "r"(a[1]), "r"(a[2]), "r"(a[3]),
          "r"(b[0]), "r"(b[1]));
}
__device__ __forceinline__ void cp16(void* dst, const void* src)
{
    uint32_t d = (uint32_t)__cvta_generic_to_shared(dst);
    asm volatile("cp.async.ca.shared.global [%0], [%1], 16;\n" :: "r"(d), "l"(src));
}
__device__ __forceinline__ unsigned encf(float f)
{
    unsigned u = __float_as_uint(f);
    return (u >> 31) ? ~u : (u | 0x80000000u);
}
__device__ __forceinline__ float decf(unsigned u)
{
    return __uint_as_float((u >> 31) ? (u & 0x7FFFFFFFu) : ~u);
}
__device__ __forceinline__ unsigned redux_max_u32(unsigned v)
{
    unsigned r;
    asm volatile("redux.sync.max.u32 %0, %1, 0xffffffff;" : "=r"(r) : "r"(v));
    return r;
}
__device__ __forceinline__ unsigned redux_min_u32(unsigned v)
{
    unsigned r;
    asm volatile("redux.sync.min.u32 %0, %1, 0xffffffff;" : "=r"(r) : "r"(v));
    return r;
}

// ---------------- prep: weights + feat transpose + zero stats/extrema --------
// blocks [0,256): weights; [256,4352): feat transpose; [4352,7424): zero emax/emin
__global__ void prep_kernel(const float* __restrict__ w0, const float* __restrict__ w1,
                            const float* __restrict__ w2, const float* __restrict__ w3,
                            const float* __restrict__ w4, const float* __restrict__ w5,
                            const float* __restrict__ feat,
                            float* __restrict__ wt, float* __restrict__ featT,
                            float* __restrict__ sum0, float* __restrict__ sq0,
                            float* __restrict__ sum1, float* __restrict__ sq1,
                            unsigned* __restrict__ emax0, unsigned* __restrict__ emin0,
                            unsigned* __restrict__ emax1, unsigned* __restrict__ emin1)
{
    int blk = blockIdx.x, tid = threadIdx.x;
    if (blk == 0) { sum0[tid] = 0.f; sq0[tid] = 0.f; }
    if (blk == 1) { sum1[tid] = 0.f; sq1[tid] = 0.f; }
    if (blk < 256) {
        const int lo[6]   = {0, 24, 40, 72, 96, 128};
        const int Os[6]   = {64, 64, 128, 64, 128, 256};
        const int Is[6]   = {67, 64, 64, 67, 64, 128};
        const int Ip[6]   = {96, 64, 64, 96, 64, 128};
        const int woff[6] = {0, 6144, 10240, 18432, 24576, 32768};
        const float* Ws[6] = {w0, w1, w2, w3, w4, w5};
        int li = 5;
#pragma unroll
        for (int i = 1; i < 6; ++i) if (blk < lo[i]) { li = i - 1; break; }
        int e = (blk - lo[li]) * 256 + tid;
        int O = Os[li], I = Is[li], Ipad = Ip[li];
        if (e < Ipad * O) {
            int k = e / O, o = e % O;
            int src;
            if (li == 0 || li == 3) {
                src = (k < 64) ? (k + 3) : ((k < 67) ? (k - 64) : -1);
            } else {
                src = (k < I) ? k : -1;
            }
            wt[woff[li] + e] = (src >= 0) ? to_tf32(Ws[li][(size_t)o * I + src]) : 0.f;
        }
    } else if (blk < 4352) {
        __shared__ float tile[32][33];
        int t = blk - 256;
        int b = t >> 9;
        int rem = t & 511;
        int c0 = (rem >> 8) * 32;
        int p0 = (rem & 255) * 32;
        int tx = tid & 31, ty = tid >> 5;
#pragma unroll
        for (int i = ty; i < 32; i += 8)
            tile[i][tx] = feat[((size_t)b * 64 + c0 + i) * 8192 + p0 + tx];
        __syncthreads();
#pragma unroll
        for (int i = ty; i < 32; i += 8)
            featT[((size_t)b * 8192 + p0 + i) * 64 + c0 + tx] = tile[tx][i];
    } else {
        size_t t = ((size_t)(blk - 4352) * 256 + tid) * 8;
        uint4 z = make_uint4(0, 0, 0, 0);
        unsigned* dst;
        size_t o;
        if (t < 1048576)      { dst = emax0; o = t; }
        else if (t < 2097152) { dst = emin0; o = t - 1048576; }
        else if (t < 4194304) { dst = emax1; o = t - 2097152; }
        else                  { dst = emin1; o = t - 4194304; }
        *(uint4*)(dst + o) = z;
        *(uint4*)(dst + o + 4) = z;
    }
}

// ---------------- farthest point sampling (mean fused, redux reductions) ------
__global__ void __launch_bounds__(1024) fps_kernel(
    const float* __restrict__ xyz, float* __restrict__ nxyz)
{
    const int b = blockIdx.x, tid = threadIdx.x;
    const int lane = tid & 31, wid = tid >> 5;
    float px[9], py[9], pz[9], dist[9];
    float msx = 0.f, msy = 0.f, msz = 0.f;
#pragma unroll
    for (int j = 0; j < 9; ++j) {
        int p = j * 1024 + tid;
        px[j] = 0.f; py[j] = 0.f; pz[j] = 0.f;
        if (p >= 1 && p < 8193) {
            const float* q = xyz + ((size_t)b * 8192 + (p - 1)) * 3;
            px[j] = q[0]; py[j] = q[1]; pz[j] = q[2];
            msx += q[0]; msy += q[1]; msz += q[2];
        }
        dist[j] = 1e10f;
    }
    __shared__ float red[96];
    __shared__ float sc[3];
    __shared__ unsigned svals[32], sbps[32];
#pragma unroll
    for (int off = 16; off; off >>= 1) {
        msx += __shfl_xor_sync(0xFFFFFFFFu, msx, off);
        msy += __shfl_xor_sync(0xFFFFFFFFu, msy, off);
        msz += __shfl_xor_sync(0xFFFFFFFFu, msz, off);
    }
    if (lane == 0) { red[wid] = msx; red[32 + wid] = msy; red[64 + wid] = msz; }
    __syncthreads();
    if (tid == 0) {
        float ax = 0.f, ay = 0.f, az = 0.f;
        for (int i = 0; i < 32; ++i) { ax += red[i]; ay += red[32 + i]; az += red[64 + i]; }
        px[0] = ax / 8192.f; py[0] = ay / 8192.f; pz[0] = az / 8192.f;
    }
    int far = 0;
    const bool has9 = (tid == 0);
    for (int t = 0; t < 1024; ++t) {
        if ((far & 1023) == tid) {
            int j = far >> 10;
            sc[0] = px[j]; sc[1] = py[j]; sc[2] = pz[j];
            float* o = nxyz + ((size_t)b * 1024 + t) * 3;
            o[0] = px[j]; o[1] = py[j]; o[2] = pz[j];
        }
        __syncthreads();
        float cx = sc[0], cy = sc[1], cz = sc[2];
        float bestv = -1.f;
        int bestj = 0;
#pragma unroll
        for (int j = 0; j < 8; ++j) {
            float dx = px[j] - cx, dy = py[j] - cy, dz = pz[j] - cz;
            float d = __fadd_rn(__fadd_rn(__fmul_rn(dx, dx), __fmul_rn(dy, dy)),
                                __fmul_rn(dz, dz));
            float nd = fminf(dist[j], d);
            dist[j] = nd;
            if (nd > bestv) { bestv = nd; bestj = j; }
        }
        if (has9) {
            float dx = px[8] - cx, dy = py[8] - cy, dz = pz[8] - cz;
            float d = __fadd_rn(__fadd_rn(__fmul_rn(dx, dx), __fmul_rn(dy, dy)),
                                __fmul_rn(dz, dz));
            float nd = fminf(dist[8], d);
            dist[8] = nd;
            if (nd > bestv) { bestv = nd; bestj = 8; }
        }
        unsigned bb_ = __float_as_uint(bestv);
        unsigned bp  = (unsigned)(bestj * 1024 + tid);
        unsigned wmax = redux_max_u32(bb_);
        unsigned cand = (bb_ == wmax) ? bp : 0xFFFFFFFFu;
        unsigned wbp  = redux_min_u32(cand);
        if (lane == 0) { svals[wid] = wmax; sbps[wid] = wbp; }
        __syncthreads();
        unsigned v = svals[lane], pb = sbps[lane];
        unsigned gmax = redux_max_u32(v);
        unsigned c2 = (v == gmax) ? pb : 0xFFFFFFFFu;
        far = (int)redux_min_u32(c2);
    }
}

// ---------------- ball query, both branches in one launch ---------------------
__global__ void __launch_bounds__(1024) ball_kernel(
    const float* __restrict__ xyz, const float* __restrict__ nxyz,
    int* __restrict__ idx0, int* __restrict__ idx1, float r2a, float r2b)
{
    extern __shared__ float sh[];
    float* sx = sh; float* sy = sh + 8192; float* sz = sh + 16384;
    int tid = threadIdx.x;
    int blk = blockIdx.x;
    int K; int* idx; float r2; int local;
    if (blk < 256) { K = 32; idx = idx0; r2 = r2a; local = blk; }
    else           { K = 64; idx = idx1; r2 = r2b; local = blk - 256; }
    int b = local >> 5;
    int sblk = (local & 31) * 32;
    for (int i = tid; i < 8192; i += 1024) {
        const float* q = xyz + ((size_t)b * 8192 + i) * 3;
        sx[i] = q[0]; sy[i] = q[1]; sz[i] = q[2];
    }
    __syncthreads();
    int wid = tid >> 5, lane = tid & 31;
    int w = b * 1024 + sblk + wid;
    float cx = nxyz[(size_t)w * 3], cy = nxyz[(size_t)w * 3 + 1], cz = nxyz[(size_t)w * 3 + 2];
    int cnt = 0, first = 0;
    int* out = idx + (size_t)w * K;
    for (int base = 0; base < 8192; base += 32) {
        int p = base + lane;
        float dx = sx[p] - cx, dy = sy[p] - cy, dz = sz[p] - cz;
        float d2 = __fadd_rn(__fadd_rn(__fmul_rn(dx, dx), __fmul_rn(dy, dy)),
                             __fmul_rn(dz, dz));
        bool in = d2 < r2;
        unsigned mask = __ballot_sync(0xFFFFFFFFu, in);
        if (cnt == 0 && mask) first = base + __ffs(mask) - 1;
        if (in) {
            int pos = cnt + __popc(mask & ((1u << lane) - 1u));
            if (pos < K) out[pos] = p;
        }
        cnt += __popc(mask);
        if (cnt >= K) break;
    }
    if (cnt < K) {
        for (int pos = cnt + lane; pos < K; pos += 32) out[pos] = first;
    }
}

// ---------------- pipelined tensor-core GEMM, 128 threads / 64x128 tile -------
struct GP {
    int O, Ipad, M, K, logK, nblk, obtiles;
    const float* Wg;
    const float* X;
    float* Y;
    const float* aa;
    const float* ad;
    float* gsum;
    float* gsq;
    unsigned* emax;
    unsigned* emin;
    const int* idxp;
};

#define WP 72
#define XP 136
template <bool FUSED>
__global__ void __launch_bounds__(128, 4) gemm_tc2_kernel(
    GP gpa, GP gpb,
    const float* __restrict__ xyzp, const float* __restrict__ nxyzp,
    const float* __restrict__ featT)
{
    extern __shared__ float sm[];
    float* Wt = sm;
    float* Xt = sm + 2 * 32 * WP;
    float* ssum = sm + 2 * 32 * WP + 2 * 32 * XP;
    float* ssq  = ssum + 64;

    GP P;
    int bid = blockIdx.x;
    if (bid < gpa.nblk) { P = gpa; } else { P = gpb; bid -= gpa.nblk; }

    const int tid = threadIdx.x, lane = tid & 31, wid = tid >> 5;
    const int warpO = wid >> 1, warpM = wid & 1;       // 2 x 2 warp grid
    const int ob = (bid % P.obtiles) * 64;
    const int mb = (bid / P.obtiles) * 128;
    const int r0 = lane >> 2, kq = lane & 3;
    const int kx = tid >> 5;                            // 0..3
    const int c4 = (tid & 31) * 4;                      // 0..124
    const int NT = P.Ipad >> 5;

    if (tid < 64) { ssum[tid] = 0.f; ssq[tid] = 0.f; }

    // fused-gather per-thread state (one sample column per thread)
    int pp = 0, bsv = 0, bb = 0;
    const float* fT = featT;
    if (FUSED) {
        int m = mb + tid;
        bsv = m >> P.logK;
        bb = bsv >> 10;
        pp = P.idxp[m];
        fT = featT + ((size_t)bb * 8192 + pp) * 64;
    }

    float acc[2][8][4];
#pragma unroll
    for (int r = 0; r < 2; ++r)
#pragma unroll
        for (int nt = 0; nt < 8; ++nt)
#pragma unroll
            for (int c = 0; c < 4; ++c) acc[r][nt][c] = 0.f;

    float4 xr[8];

    auto ldgX = [&](int t) {
        if (FUSED) {
            if (t < 2) {
#pragma unroll
                for (int l = 0; l < 8; ++l)
                    xr[l] = *(const float4*)(fT + t * 32 + l * 4);
            } else {
                const float* q = xyzp + ((size_t)bb * 8192 + pp) * 3;
                const float* c = nxyzp + (size_t)bsv * 3;
                xr[0] = make_float4(q[0], q[1], q[2], 0.f);
                xr[1] = make_float4(c[0], c[1], c[2], 0.f);
            }
        } else {
#pragma unroll
            for (int l = 0; l < 8; ++l) {
                int gk = t * 32 + l * 4 + kx;
                xr[l] = *(const float4*)(P.X + (size_t)gk * P.M + mb + c4);
            }
        }
    };
    auto stsX = [&](int t, int st) {
        float* Xs = Xt + st * (32 * XP);
        if (FUSED) {
            if (t < 2) {
#pragma unroll
                for (int l = 0; l < 8; ++l) {
                    Xs[(l * 4 + 0) * XP + tid] = to_tf32(xr[l].x);
                    Xs[(l * 4 + 1) * XP + tid] = to_tf32(xr[l].y);
                    Xs[(l * 4 + 2) * XP + tid] = to_tf32(xr[l].z);
                    Xs[(l * 4 + 3) * XP + tid] = to_tf32(xr[l].w);
                }
            } else {
                Xs[0 * XP + tid] = to_tf32(xr[0].x - xr[1].x);
                Xs[1 * XP + tid] = to_tf32(xr[0].y - xr[1].y);
                Xs[2 * XP + tid] = to_tf32(xr[0].z - xr[1].z);
#pragma unroll
                for (int k = 3; k < 32; ++k) Xs[k * XP + tid] = 0.f;
            }
        } else {
#pragma unroll
            for (int l = 0; l < 8; ++l) {
                int k = l * 4 + kx;
                float4 v = xr[l];
                if (P.aa) {
                    int gk = t * 32 + k;
                    float A_ = P.aa[gk], D_ = P.ad[gk];
                    v.x = fmaxf(v.x * A_ + D_, 0.f);
                    v.y = fmaxf(v.y * A_ + D_, 0.f);
                    v.z = fmaxf(v.z * A_ + D_, 0.f);
                    v.w = fmaxf(v.w * A_ + D_, 0.f);
                }
                Xs[k * XP + c4 + 0] = to_tf32(v.x);
                Xs[k * XP + c4 + 1] = to_tf32(v.y);
                Xs[k * XP + c4 + 2] = to_tf32(v.z);
                Xs[k * XP + c4 + 3] = to_tf32(v.w);
            }
        }
    };
    auto cpW = [&](int t, int st) {
        float* Ws = Wt + st * (32 * WP);
#pragma unroll
        for (int l = 0; l < 4; ++l) {
            int e = l * 128 + tid;
            int k = e >> 4, o4 = (e & 15) * 4;
            cp16(&Ws[k * WP + o4], P.Wg + (size_t)(t * 32 + k) * P.O + ob + o4);
        }
    };

    ldgX(0);
    cpW(0, 0);
    asm volatile("cp.async.commit_group;\n");
    asm volatile("cp.async.wait_group 0;\n");
    stsX(0, 0);
    if (NT > 1) ldgX(1);
    __syncthreads();

    for (int t = 0; t < NT; ++t) {
        int cur = t & 1, nxt = cur ^ 1;
        if (t + 1 < NT) {
            stsX(t + 1, nxt);
            cpW(t + 1, nxt);
            asm volatile("cp.async.commit_group;\n");
        }
        if (t + 2 < NT) ldgX(t + 2);

        const float* Wc = Wt + cur * (32 * WP);
        const float* Xc = Xt + cur * (32 * XP);
#pragma unroll
        for (int k8 = 0; k8 < 4; ++k8) {
            int kb = k8 * 8;
            uint32_t afr[2][4], bfr[8][2];
#pragma unroll
            for (int r = 0; r < 2; ++r) {
                int o = warpO * 32 + r * 16 + r0;
                afr[r][0] = __float_as_uint(Wc[(kb + kq) * WP + o]);
                afr[r][1] = __float_as_uint(Wc[(kb + kq) * WP + o + 8]);
                afr[r][2] = __float_as_uint(Wc[(kb + kq + 4) * WP + o]);
                afr[r][3] = __float_as_uint(Wc[(kb + kq + 4) * WP + o + 8]);
            }
#pragma unroll
            for (int nt = 0; nt < 8; ++nt) {
                int m = warpM * 64 + nt * 8 + r0;
                bfr[nt][0] = __float_as_uint(Xc[(kb + kq) * XP + m]);
                bfr[nt][1] = __float_as_uint(Xc[(kb + kq + 4) * XP + m]);
            }
#pragma unroll
            for (int r = 0; r < 2; ++r)
#pragma unroll
                for (int nt = 0; nt < 8; ++nt)
                    mma_tf32(acc[r][nt], afr[r], bfr[nt]);
        }
        if (t + 1 < NT) asm volatile("cp.async.wait_group 0;\n");
        __syncthreads();
    }

    // --- epilogue ---
#pragma unroll
    for (int r = 0; r < 2; ++r) {
#pragma unroll
        for (int half = 0; half < 2; ++half) {
            int ol = warpO * 32 + r * 16 + r0 + half * 8;
            float s = 0.f, q = 0.f;
            if (P.Y) {
                size_t rowoff = (size_t)(ob + ol) * P.M + mb + warpM * 64 + kq * 2;
#pragma unroll
                for (int nt = 0; nt < 8; ++nt) {
                    float v0 = acc[r][nt][half * 2 + 0];
                    float v1 = acc[r][nt][half * 2 + 1];
                    *(float2*)(P.Y + rowoff + nt * 8) = make_float2(v0, v1);
                    s += v0 + v1;
                    q += v0 * v0 + v1 * v1;
                }
            } else {
                int ntg = P.K >> 3;
                for (int g0 = 0; g0 < 8; g0 += ntg) {
                    float mxv = -3.4e38f, mnv = 3.4e38f;
                    for (int nt = g0; nt < g0 + ntg; ++nt) {
                        float v0 = acc[r][nt][half * 2 + 0];
                        float v1 = acc[r][nt][half * 2 + 1];
                        s += v0 + v1;
                        q += v0 * v0 + v1 * v1;
                        mxv = fmaxf(mxv, fmaxf(v0, v1));
                        mnv = fminf(mnv, fminf(v0, v1));
                    }
                    mxv = fmaxf(mxv, __shfl_xor_sync(0xFFFFFFFFu, mxv, 1));
                    mnv = fminf(mnv, __shfl_xor_sync(0xFFFFFFFFu, mnv, 1));
                    mxv = fmaxf(mxv, __shfl_xor_sync(0xFFFFFFFFu, mxv, 2));
                    mnv = fminf(mnv, __shfl_xor_sync(0xFFFFFFFFu, mnv, 2));
                    if (kq == 0) {
                        int bs = (mb + warpM * 64 + g0 * 8) >> P.logK;
                        atomicMax(&P.emax[(size_t)(ob + ol) * 8192 + bs], encf(mxv));
                        atomicMax(&P.emin[(size_t)(ob + ol) * 8192 + bs], encf(-mnv));
                    }
                }
            }
            s += __shfl_xor_sync(0xFFFFFFFFu, s, 1);
            q += __shfl_xor_sync(0xFFFFFFFFu, q, 1);
            s += __shfl_xor_sync(0xFFFFFFFFu, s, 2);
            q += __shfl_xor_sync(0xFFFFFFFFu, q, 2);
            if (kq == 0) {
                atomicAdd(&ssum[ol], s);
                atomicAdd(&ssq[ol], q);
            }
        }
    }
    __syncthreads();
    if (tid < 64) {
        atomicAdd(&P.gsum[ob + tid], ssum[tid]);
        atomicAdd(&P.gsq[ob + tid], ssq[tid]);
    }
}

// ---------------- BN finalize, both branches (grid 2) -------------------------
__global__ void finalize_kernel(
    float* sum0, float* sq0, const float* g0, const float* bb0,
    float* aa0, float* ad0, int O0, float invn0,
    float* sum1, float* sq1, const float* g1, const float* bb1,
    float* aa1, float* ad1, int O1, float invn1)
{
    float *sum, *sq, *aa, *ad; const float *g, *bb; int O; float invn;
    if (blockIdx.x == 0) { sum = sum0; sq = sq0; g = g0; bb = bb0; aa = aa0; ad = ad0; O = O0; invn = invn0; }
    else                 { sum = sum1; sq = sq1; g = g1; bb = bb1; aa = aa1; ad = ad1; O = O1; invn = invn1; }
    int c = threadIdx.x;
    if (c < O) {
        float m = sum[c] * invn;
        float v = sq[c] * invn - m * m;
        float a = g[c] / sqrtf(v + 1e-5f);
        aa[c] = a;
        ad[c] = bb[c] - m * a;
    }
    if (c < 256) { sum[c] = 0.f; sq[c] = 0.f; }
}

// ---------------- final: decode max/min + last affine+relu, both branches -----
__global__ void maxfin_kernel(
    const unsigned* __restrict__ emax0, const unsigned* __restrict__ emin0,
    const unsigned* __restrict__ emax1, const unsigned* __restrict__ emin1,
    const float* __restrict__ aa0, const float* __restrict__ ad0,
    const float* __restrict__ aa1, const float* __restrict__ ad1,
    float* __restrict__ out)
{
    int gid = blockIdx.x * 256 + threadIdx.x;
    const unsigned *emax, *emin; const float *aa, *ad;
    int O, coff, id;
    if (gid < 1048576) {
        id = gid; O = 128; coff = 0; emax = emax0; emin = emin0; aa = aa0; ad = ad0;
    } else {
        id = gid - 1048576;
        O = 256; coff = 128; emax = emax1; emin = emin1; aa = aa1; ad = ad1;
    }
    int s = id & 1023;
    int c = (id >> 10) % O;
    int b = id / (O * 1024);
    int bs = b * 1024 + s;
    float a = aa[c], d = ad[c];
    size_t off = (size_t)c * 8192 + bs;
    float y = (a >= 0.f) ? decf(emax[off]) : -decf(emin[off]);
    out[((size_t)b * 384 + coff + c) * 1024 + s] = fmaxf(y * a + d, 0.f);
}

// ---------------- host launch ------------------------------------------------
extern "C" void kernel_launch(void* const* d_in, const int* in_sizes, int n_in,
                              void* d_out, int out_size)
{
    (void)in_sizes; (void)n_in; (void)out_size;
    const float* xyz  = (const float*)d_in[0];
    const float* feat = (const float*)d_in[1];
    const float* W[2][3]; const float* G[2][3]; const float* Bb[2][3];
    for (int bi = 0; bi < 2; ++bi)
        for (int li = 0; li < 3; ++li) {
            W[bi][li]  = (const float*)d_in[2 + bi * 9 + li * 3 + 0];
            G[bi][li]  = (const float*)d_in[2 + bi * 9 + li * 3 + 1];
            Bb[bi][li] = (const float*)d_in[2 + bi * 9 + li * 3 + 2];
        }
    float* out      = (float*)d_out;
    float* nxyz     = out;            // (8,1024,3)
    float* feat_out = out + 24576;    // (8,384,1024)

    float *bufA, *bufB, *featT, *wt;
    float *sum0, *sq0, *sum1, *sq1, *aa0, *ad0, *aa1, *ad1;
    int *idx0, *idx1;
    unsigned *emax0, *emin0, *emax1, *emin1;
    cudaGetSymbolAddress((void**)&bufA, g_bufA);
    cudaGetSymbolAddress((void**)&bufB, g_bufB);
    cudaGetSymbolAddress((void**)&featT, g_featT);
    cudaGetSymbolAddress((void**)&wt, g_wt);
    cudaGetSymbolAddress((void**)&sum0, g_sum0);
    cudaGetSymbolAddress((void**)&sq0, g_sq0);
    cudaGetSymbolAddress((void**)&sum1, g_sum1);
    cudaGetSymbolAddress((void**)&sq1, g_sq1);
    cudaGetSymbolAddress((void**)&aa0, g_affa0);
    cudaGetSymbolAddress((void**)&ad0, g_affd0);
    cudaGetSymbolAddress((void**)&aa1, g_affa1);
    cudaGetSymbolAddress((void**)&ad1, g_affd1);
    cudaGetSymbolAddress((void**)&idx0, g_idx0);
    cudaGetSymbolAddress((void**)&idx1, g_idx1);
    cudaGetSymbolAddress((void**)&emax0, g_emax0);
    cudaGetSymbolAddress((void**)&emin0, g_emin0);
    cudaGetSymbolAddress((void**)&emax1, g_emax1);
    cudaGetSymbolAddress((void**)&emin1, g_emin1);

    const int SMEM_GEMM = (2 * 32 * WP + 2 * 32 * XP + 128) * 4;  // 53760 B
    cudaFuncSetAttribute(gemm_tc2_kernel<true>,
                         cudaFuncAttributeMaxDynamicSharedMemorySize, SMEM_GEMM);
    cudaFuncSetAttribute(gemm_tc2_kernel<false>,
                         cudaFuncAttributeMaxDynamicSharedMemorySize, SMEM_GEMM);
    const int SMEM_BALL = 3 * 8192 * 4;                           // 98304 B
    cudaFuncSetAttribute(ball_kernel,
                         cudaFuncAttributeMaxDynamicSharedMemorySize, SMEM_BALL);

    const int M0 = 262144, M1 = 524288;
    const float invn0 = 1.f / (float)M0, invn1 = 1.f / (float)M1;
    float* YB0 = bufB;
    float* YB1 = bufB + (size_t)64 * M0;
    float* YA0 = bufA;
    float* YA1 = bufA + (size_t)64 * M0;

    prep_kernel<<<7424, 256>>>(W[0][0], W[0][1], W[0][2], W[1][0], W[1][1], W[1][2],
                               feat, wt, featT, sum0, sq0, sum1, sq1,
                               emax0, emin0, emax1, emin1);
    fps_kernel<<<8, 1024>>>(xyz, nxyz);
    ball_kernel<<<512, 1024, SMEM_BALL>>>(xyz, nxyz, idx0, idx1,
                                          (float)(0.4 * 0.4), (float)(0.8 * 0.8));

    // ---- L0 (fused gather) ----
    {
        GP a = {64, 96, M0, 32, 5, 2048, 1, wt + 0,     nullptr, YB0,
                nullptr, nullptr, sum0, sq0, nullptr, nullptr, idx0};
        GP b = {64, 96, M1, 64, 6, 4096, 1, wt + 18432, nullptr, YB1,
                nullptr, nullptr, sum1, sq1, nullptr, nullptr, idx1};
        gemm_tc2_kernel<true><<<6144, 128, SMEM_GEMM>>>(a, b, xyz, nxyz, featT);
        finalize_kernel<<<2, 256>>>(sum0, sq0, G[0][0], Bb[0][0], aa0, ad0, 64, invn0,
                                    sum1, sq1, G[1][0], Bb[1][0], aa1, ad1, 64, invn1);
    }
    // ---- L1 ----
    {
        GP a = {64,  64, M0, 32, 5, 2048, 1, wt + 6144,  YB0, YA0,
                aa0, ad0, sum0, sq0, nullptr, nullptr, nullptr};
        GP b = {128, 64, M1, 64, 6, 8192, 2, wt + 24576, YB1, YA1,
                aa1, ad1, sum1, sq1, nullptr, nullptr, nullptr};
        gemm_tc2_kernel<false><<<10240, 128, SMEM_GEMM>>>(a, b, xyz, nxyz, featT);
        finalize_kernel<<<2, 256>>>(sum0, sq0, G[0][1], Bb[0][1], aa0, ad0, 64, invn0,
                                    sum1, sq1, G[1][1], Bb[1][1], aa1, ad1, 128, invn1);
    }
    // ---- L2 (fused max/min epilogue, no Y write) ----
    {
        GP a = {128, 64,  M0, 32, 5, 4096,  2, wt + 10240, YA0, nullptr,
                aa0, ad0, sum0, sq0, emax0, emin0, nullptr};
        GP b = {256, 128, M1, 64, 6, 16384, 4, wt + 32768, YA1, nullptr,
                aa1, ad1, sum1, sq1, emax1, emin1, nullptr};
        gemm_tc2_kernel<false><<<20480, 128, SMEM_GEMM>>>(a, b, xyz, nxyz, featT);
        finalize_kernel<<<2, 256>>>(sum0, sq0, G[0][2], Bb[0][2], aa0, ad0, 128, invn0,
                                    sum1, sq1, G[1][2], Bb[1][2], aa1, ad1, 256, invn1);
    }
    // ---- decode + final affine + relu -> output (both branches) ----
    maxfin_kernel<<<12288, 256>>>(emax0, emin0, emax1, emin1,
                                  aa0, ad0, aa1, ad1, feat_out);
}